// round 9
// baseline (speedup 1.0000x reference)
#include <cuda_runtime.h>
#include <cuda_fp16.h>
#include <cstdint>

// Problem constants: N=50000 nodes, E=800000 edges, D=C=128, H=1
#define NMAX 50000
#define EMAX 800000
#define EE   (EMAX + NMAX)
constexpr int DDIM = 128;

constexpr int XS_STRIDE = 132;   // X smem pad: bank = (4*gid + tig) = lane  -> conflict-free
constexpr int WS_STRIDE = 136;   // W smem pad: bank = (8*tig + gid)         -> conflict-free
constexpr int WIMG = 128 * WS_STRIDE;  // 17408 floats per W image
constexpr int SCAN_FLAG = 1 << 30;

// ---------------- static device scratch ----------------
__device__ __half g_xl[(size_t)NMAX * 128];   // transformed features, fp16
__device__ float  g_h [(size_t)NMAX * 128];   // layer-1 output (fp32)
__device__ float  g_as[NMAX];
__device__ float  g_ad[NMAX];
__device__ int    g_deg[NMAX];
__device__ int    g_rowptr[NMAX + 1];
__device__ int    g_cursor[NMAX];
__device__ int    g_csrsrc[EE];
__device__ int    g_bsum[256];
// W (per layer) as tf32-rounded hi/lo fp32, [k][n] with pad stride WS_STRIDE
__device__ __align__(16) float g_whi[2][WIMG];
__device__ __align__(16) float g_wlo[2][WIMG];

// ---------------- helpers ----------------
__device__ __forceinline__ uint32_t f2tf32(float v) {
    uint32_t u;
    asm("cvt.rna.tf32.f32 %0, %1;" : "=r"(u) : "f"(v));
    return u;
}
__device__ __forceinline__ void mma_tf32(float c[4], const uint32_t a[4], uint32_t b0, uint32_t b1) {
    asm volatile(
        "mma.sync.aligned.m16n8k8.row.col.f32.tf32.tf32.f32 "
        "{%0,%1,%2,%3}, {%4,%5,%6,%7}, {%8,%9}, {%0,%1,%2,%3};"
        : "+f"(c[0]), "+f"(c[1]), "+f"(c[2]), "+f"(c[3])
        : "r"(a[0]), "r"(a[1]), "r"(a[2]), "r"(a[3]), "r"(b0), "r"(b1));
}

// ============================================================================
// Fused prep: blocks [0,128) convert W -> tf32 hi/lo images;
// blocks [128, 128+nb) init g_deg = 1 (self-loop pre-counted); block 128 also
// zeroes g_bsum (scan state).
// ============================================================================
__global__ void prep_kernel(const float* __restrict__ W1, const float* __restrict__ W2, int n) {
    int b = blockIdx.x, t = threadIdx.x;
    if (b < 128) {
        int idx = b * 256 + t;                 // 0..32767
        int layer = idx >> 14;
        int e = idx & 16383;                   // k*128 + n (coalesced read)
        int k = e >> 7, nn = e & 127;
        float v = (layer ? W2 : W1)[e];
        uint32_t hi = f2tf32(v);
        float lo_f = v - __uint_as_float(hi);
        uint32_t lo = f2tf32(lo_f);
        g_whi[layer][k * WS_STRIDE + nn] = __uint_as_float(hi);
        g_wlo[layer][k * WS_STRIDE + nn] = __uint_as_float(lo);
    } else {
        int i = (b - 128) * 256 + t;
        if (i < n) g_deg[i] = 1;               // self loop
        if (b == 128) g_bsum[t] = 0;
    }
}

// ============================================================================
// CSR build
// ============================================================================
__global__ void count_deg_kernel(const int* __restrict__ ei, int E) {
    int i = blockIdx.x * blockDim.x + threadIdx.x;
    if (i < E) atomicAdd(&g_deg[ei[E + i]], 1);
}

// Single-kernel exclusive scan (publish + lookback). All blocks publish before
// spinning; 196 tiny blocks are all co-resident -> deadlock-free.
__global__ void scan_rowptr_kernel(int n) {
    __shared__ int sh[256];
    __shared__ int red[256];
    int t = threadIdx.x, b = blockIdx.x;
    int i = b * 256 + t;
    int v = (i < n) ? g_deg[i] : 0;
    sh[t] = v;
    __syncthreads();
    for (int o = 1; o < 256; o <<= 1) {         // Hillis-Steele inclusive
        int u = (t >= o) ? sh[t - o] : 0;
        __syncthreads();
        sh[t] += u;
        __syncthreads();
    }
    if (t == 255) atomicExch(&g_bsum[b], sh[255] + SCAN_FLAG);
    // lookback: lane-parallel poll of all predecessor aggregates
    int agg = 0;
    for (int p = t; p < b; p += 256) {
        int val;
        do { val = *(volatile int*)&g_bsum[p]; } while (val < SCAN_FLAG);
        agg += val - SCAN_FLAG;
    }
    red[t] = agg;
    __syncthreads();
    for (int o = 128; o; o >>= 1) {
        if (t < o) red[t] += red[t + o];
        __syncthreads();
    }
    int excl = red[0] + sh[t] - v;
    if (i < n) {
        g_rowptr[i] = excl;
        g_cursor[i] = excl;
        if (i == n - 1) g_rowptr[n] = excl + v;
    }
}

__global__ void scatter_edges_kernel(const int* __restrict__ ei, int E, int n) {
    int i = blockIdx.x * blockDim.x + threadIdx.x;
    if (i < E) {
        int s = ei[i];
        int d = ei[E + i];
        g_csrsrc[atomicAdd(&g_cursor[d], 1)] = s;
    } else if (i < E + n) {
        int v = i - E;
        g_csrsrc[atomicAdd(&g_cursor[v], 1)] = v;   // self loop
    }
}

// ============================================================================
// Tensor-core GEMM + attention: XL = X @ W via tf32-split mma.sync (3 passes),
// fused a_s/a_d epilogue. CTA = 128 rows, 8 warps (16 rows/warp).
// XL stored as fp16 (halves aggregate gather traffic).
// ============================================================================
constexpr uint32_t SMEM_FLOATS = 128 * XS_STRIDE + 2 * WIMG;   // 51712
constexpr uint32_t SMEM_BYTES  = SMEM_FLOATS * 4;              // 206848

__global__ __launch_bounds__(256) void gemm_mma_kernel(
    const float* __restrict__ X,
    const float* __restrict__ Whi, const float* __restrict__ Wlo,
    const float* __restrict__ atts, const float* __restrict__ attd,
    __half* __restrict__ XL, int n)
{
    extern __shared__ float sm[];
    float* Xs = sm;                       // 128 x 132
    float* Wh = sm + 128 * XS_STRIDE;     // 128 x 136
    float* Wl = Wh + WIMG;

    int tid = threadIdx.x, lane = tid & 31, warp = tid >> 5;
    int gid = lane >> 2, tig = lane & 3;
    int row0 = blockIdx.x * 128;

    // W tiles: linear float4 copies of the padded images (L2-broadcast across CTAs)
    {
        const float4* gh = (const float4*)Whi;
        const float4* gl = (const float4*)Wlo;
        float4* sh = (float4*)Wh;
        float4* sl = (float4*)Wl;
#pragma unroll
        for (int i = 0; i < 17; i++) {
            int idx = tid + i * 256;
            if (idx < WIMG / 4) { sh[idx] = gh[idx]; sl[idx] = gl[idx]; }
        }
    }
    // X tile: coalesced float4 loads, padded-stride stores
    {
        const float4* X4 = (const float4*)X;
#pragma unroll
        for (int i = 0; i < 16; i++) {
            int idx = tid + i * 256;        // 128 rows x 32 float4
            int r = idx >> 5, c = idx & 31;
            float4 v = make_float4(0.f, 0.f, 0.f, 0.f);
            if (row0 + r < n) v = X4[(size_t)(row0 + r) * 32 + c];
            *(float4*)(Xs + r * XS_STRIDE + c * 4) = v;
        }
    }
    __syncthreads();

    const int rbase = warp * 16;
    float c[16][4];
#pragma unroll
    for (int nt = 0; nt < 16; nt++) { c[nt][0] = c[nt][1] = c[nt][2] = c[nt][3] = 0.f; }

    const float* xr0 = Xs + (rbase + gid) * XS_STRIDE + tig;
    const float* xr1 = xr0 + 8 * XS_STRIDE;

    for (int ks = 0; ks < 16; ks++) {
        int k0 = ks * 8;
        float x0 = xr0[k0], x1 = xr1[k0], x2 = xr0[k0 + 4], x3 = xr1[k0 + 4];
        uint32_t ah[4], al[4];
        ah[0] = f2tf32(x0); al[0] = f2tf32(x0 - __uint_as_float(ah[0]));
        ah[1] = f2tf32(x1); al[1] = f2tf32(x1 - __uint_as_float(ah[1]));
        ah[2] = f2tf32(x2); al[2] = f2tf32(x2 - __uint_as_float(ah[2]));
        ah[3] = f2tf32(x3); al[3] = f2tf32(x3 - __uint_as_float(ah[3]));

        const float* wh0 = Wh + (k0 + tig) * WS_STRIDE + gid;
        const float* wl0 = Wl + (k0 + tig) * WS_STRIDE + gid;
#pragma unroll
        for (int nt = 0; nt < 16; nt++) {
            int nb = nt * 8;
            uint32_t bh0 = __float_as_uint(wh0[nb]);
            uint32_t bh1 = __float_as_uint(wh0[nb + 4 * WS_STRIDE]);
            uint32_t bl0 = __float_as_uint(wl0[nb]);
            uint32_t bl1 = __float_as_uint(wl0[nb + 4 * WS_STRIDE]);
            mma_tf32(c[nt], ah, bh0, bh1);
            mma_tf32(c[nt], ah, bl0, bl1);
            mma_tf32(c[nt], al, bh0, bh1);
        }
    }

    // Epilogue: attention dots (fp32 accumulators) + fp16 XL stores.
    float ps0 = 0.f, pd0 = 0.f, ps1 = 0.f, pd1 = 0.f;
#pragma unroll
    for (int nt = 0; nt < 16; nt++) {
        int col = nt * 8 + tig * 2;
        float a0 = __ldg(atts + col), a1 = __ldg(atts + col + 1);
        float d0 = __ldg(attd + col), d1 = __ldg(attd + col + 1);
        ps0 = fmaf(c[nt][0], a0, fmaf(c[nt][1], a1, ps0));
        pd0 = fmaf(c[nt][0], d0, fmaf(c[nt][1], d1, pd0));
        ps1 = fmaf(c[nt][2], a0, fmaf(c[nt][3], a1, ps1));
        pd1 = fmaf(c[nt][2], d0, fmaf(c[nt][3], d1, pd1));
    }
#pragma unroll
    for (int o = 1; o <= 2; o <<= 1) {
        ps0 += __shfl_xor_sync(0xffffffffu, ps0, o);
        pd0 += __shfl_xor_sync(0xffffffffu, pd0, o);
        ps1 += __shfl_xor_sync(0xffffffffu, ps1, o);
        pd1 += __shfl_xor_sync(0xffffffffu, pd1, o);
    }
    int r0 = row0 + rbase + gid;
    int r1 = r0 + 8;
    if (tig == 0) {
        if (r0 < n) { g_as[r0] = ps0; g_ad[r0] = pd0; }
        if (r1 < n) { g_as[r1] = ps1; g_ad[r1] = pd1; }
    }
    if (r0 < n) {
        __half2* dst = (__half2*)(XL + (size_t)r0 * 128) + tig;   // half2 idx: nt*4 + tig
#pragma unroll
        for (int nt = 0; nt < 16; nt++)
            dst[nt * 4] = __floats2half2_rn(c[nt][0], c[nt][1]);
    }
    if (r1 < n) {
        __half2* dst = (__half2*)(XL + (size_t)r1 * 128) + tig;
#pragma unroll
        for (int nt = 0; nt < 16; nt++)
            dst[nt * 4] = __floats2half2_rn(c[nt][2], c[nt][3]);
    }
}

// ============================================================================
// Aggregation: one warp per dst node, fp16 XL gathers (256B/row), fp32 accum.
//   w_e = exp(leakyrelu(a_s[src_e] + a_d[v]))
//   out[v] = relu( (sum_e w_e * XL[src_e]) / (sum_e w_e + 1e-16) + b )
// ============================================================================
__device__ __forceinline__ float edge_w(float as_v, float adv) {
    float t = as_v + adv;
    t = t > 0.f ? t : 0.2f * t;
    return __expf(t);
}
__device__ __forceinline__ void fma_row(float4& acc, float w, uint2 u) {
    float2 f0 = __half22float2(*(const __half2*)&u.x);
    float2 f1 = __half22float2(*(const __half2*)&u.y);
    acc.x = fmaf(w, f0.x, acc.x); acc.y = fmaf(w, f0.y, acc.y);
    acc.z = fmaf(w, f1.x, acc.z); acc.w = fmaf(w, f1.y, acc.w);
}

__global__ __launch_bounds__(256) void aggregate_kernel(
    const __half* __restrict__ XL, const float* __restrict__ bias,
    float* __restrict__ OUT, int n)
{
    int wid = blockIdx.x * 8 + (threadIdx.x >> 5);
    int lane = threadIdx.x & 31;
    if (wid >= n) return;

    int beg = g_rowptr[wid];
    int end = g_rowptr[wid + 1];
    float adv = g_ad[wid];
    float4 acc = make_float4(0.f, 0.f, 0.f, 0.f);
    float z = 0.f;
    const uint2* XH = (const uint2*)XL;          // 8B per lane = 4 halfs

    int j = beg;
    for (; j + 4 <= end; j += 4) {
        int s0 = g_csrsrc[j],     s1 = g_csrsrc[j + 1];
        int s2 = g_csrsrc[j + 2], s3 = g_csrsrc[j + 3];
        float w0 = edge_w(g_as[s0], adv);
        float w1 = edge_w(g_as[s1], adv);
        float w2 = edge_w(g_as[s2], adv);
        float w3 = edge_w(g_as[s3], adv);
        uint2 u0 = XH[(size_t)s0 * 32 + lane];
        uint2 u1 = XH[(size_t)s1 * 32 + lane];
        uint2 u2 = XH[(size_t)s2 * 32 + lane];
        uint2 u3 = XH[(size_t)s3 * 32 + lane];
        fma_row(acc, w0, u0);
        fma_row(acc, w1, u1);
        fma_row(acc, w2, u2);
        fma_row(acc, w3, u3);
        z += (w0 + w1) + (w2 + w3);
    }
    for (; j < end; j++) {
        int s = g_csrsrc[j];
        float w = edge_w(g_as[s], adv);
        uint2 u = XH[(size_t)s * 32 + lane];
        fma_row(acc, w, u);
        z += w;
    }

    float inv = 1.f / (z + 1e-16f);
    float4 bv = ((const float4*)bias)[lane];
    float4 o;
    o.x = fmaxf(fmaf(acc.x, inv, bv.x), 0.f);
    o.y = fmaxf(fmaf(acc.y, inv, bv.y), 0.f);
    o.z = fmaxf(fmaf(acc.z, inv, bv.z), 0.f);
    o.w = fmaxf(fmaf(acc.w, inv, bv.w), 0.f);
    ((float4*)OUT)[(size_t)wid * 32 + lane] = o;
}

// ============================================================================
// Launch (8 kernels)
// ============================================================================
extern "C" void kernel_launch(void* const* d_in, const int* in_sizes, int n_in,
                              void* d_out, int out_size)
{
    const float* x   = (const float*)d_in[0];
    const int*   ei  = (const int*)d_in[1];
    const float* W1  = (const float*)d_in[2];
    const float* as1 = (const float*)d_in[3];
    const float* ad1 = (const float*)d_in[4];
    const float* b1  = (const float*)d_in[5];
    const float* W2  = (const float*)d_in[6];
    const float* as2 = (const float*)d_in[7];
    const float* ad2 = (const float*)d_in[8];
    const float* b2  = (const float*)d_in[9];

    int n = in_sizes[0] / DDIM;   // 50000
    int E = in_sizes[1] / 2;      // 800000
    int ee = E + n;
    float* out = (float*)d_out;

    void *xl_p, *h_p, *wh_p, *wl_p;
    cudaGetSymbolAddress(&xl_p, g_xl);
    cudaGetSymbolAddress(&h_p,  g_h);
    cudaGetSymbolAddress(&wh_p, g_whi);
    cudaGetSymbolAddress(&wl_p, g_wlo);
    __half* xl = (__half*)xl_p;
    float*  h  = (float*)h_p;
    const float* whi = (const float*)wh_p;
    const float* wlo = (const float*)wl_p;

    cudaFuncSetAttribute(gemm_mma_kernel, cudaFuncAttributeMaxDynamicSharedMemorySize, SMEM_BYTES);

    int nb = (n + 255) / 256;     // 196

    // --- prep (W images + deg=1 init + scan-state zero) & CSR build ---
    prep_kernel<<<128 + nb, 256>>>(W1, W2, n);
    count_deg_kernel<<<(E + 255) / 256, 256>>>(ei, E);
    scan_rowptr_kernel<<<nb, 256>>>(n);
    scatter_edges_kernel<<<(ee + 255) / 256, 256>>>(ei, E, n);

    int gblocks = (n + 127) / 128;

    // --- Layer 1 ---
    gemm_mma_kernel<<<gblocks, 256, SMEM_BYTES>>>(x, whi, wlo, as1, ad1, xl, n);
    aggregate_kernel<<<(n + 7) / 8, 256>>>(xl, b1, h, n);

    // --- Layer 2 ---
    gemm_mma_kernel<<<gblocks, 256, SMEM_BYTES>>>(h, whi + WIMG, wlo + WIMG, as2, ad2, xl, n);
    aggregate_kernel<<<(n + 7) / 8, 256>>>(xl, b2, out, n);
}

// round 10
// speedup vs baseline: 1.0561x; 1.0561x over previous
#include <cuda_runtime.h>
#include <cstdint>

// Problem constants: N=50000 nodes, E=800000 edges, D=C=128, H=1
#define NMAX 50000
#define EMAX 800000
#define EE   (EMAX + NMAX)
constexpr int DDIM = 128;

constexpr int XS_STRIDE = 132;   // X smem pad: bank = (4*gid + tig) = lane  -> conflict-free
constexpr int WS_STRIDE = 136;   // W smem pad: bank = (8*tig + gid)         -> conflict-free
constexpr int WIMG = 128 * WS_STRIDE;  // 17408 floats per W image
constexpr int SCAN_FLAG = 1 << 30;
constexpr int GEMM_GRID = 148;   // persistent: one CTA per SM

// ---------------- static device scratch ----------------
__device__ float g_xl[(size_t)NMAX * 128];
__device__ float g_h [(size_t)NMAX * 128];
__device__ float g_as[NMAX];
__device__ float g_ad[NMAX];
__device__ int   g_deg[NMAX];
__device__ int   g_rowptr[NMAX + 1];
__device__ int   g_cursor[NMAX];
__device__ int   g_csrsrc[EE];
__device__ int   g_bsum[256];
// W (per layer) as tf32-rounded hi/lo fp32, [k][n] with pad stride WS_STRIDE
__device__ __align__(16) float g_whi[2][WIMG];
__device__ __align__(16) float g_wlo[2][WIMG];

// ---------------- helpers ----------------
__device__ __forceinline__ uint32_t f2tf32(float v) {
    uint32_t u;
    asm("cvt.rna.tf32.f32 %0, %1;" : "=r"(u) : "f"(v));
    return u;
}
__device__ __forceinline__ void mma_tf32(float c[4], const uint32_t a[4], uint32_t b0, uint32_t b1) {
    asm volatile(
        "mma.sync.aligned.m16n8k8.row.col.f32.tf32.tf32.f32 "
        "{%0,%1,%2,%3}, {%4,%5,%6,%7}, {%8,%9}, {%0,%1,%2,%3};"
        : "+f"(c[0]), "+f"(c[1]), "+f"(c[2]), "+f"(c[3])
        : "r"(a[0]), "r"(a[1]), "r"(a[2]), "r"(a[3]), "r"(b0), "r"(b1));
}

// ============================================================================
// Fused prep: blocks [0,128) convert W -> tf32 hi/lo images;
// blocks [128, 128+nb) init g_deg = 1 (self-loop pre-counted); block 128 also
// zeroes g_bsum (scan state).
// ============================================================================
__global__ void prep_kernel(const float* __restrict__ W1, const float* __restrict__ W2, int n) {
    int b = blockIdx.x, t = threadIdx.x;
    if (b < 128) {
        int idx = b * 256 + t;                 // 0..32767
        int layer = idx >> 14;
        int e = idx & 16383;                   // k*128 + n (coalesced read)
        int k = e >> 7, nn = e & 127;
        float v = (layer ? W2 : W1)[e];
        uint32_t hi = f2tf32(v);
        float lo_f = v - __uint_as_float(hi);
        uint32_t lo = f2tf32(lo_f);
        g_whi[layer][k * WS_STRIDE + nn] = __uint_as_float(hi);
        g_wlo[layer][k * WS_STRIDE + nn] = __uint_as_float(lo);
    } else {
        int i = (b - 128) * 256 + t;
        if (i < n) g_deg[i] = 1;               // self loop
        if (b == 128) g_bsum[t] = 0;
    }
}

// ============================================================================
// CSR build
// ============================================================================
__global__ void count_deg_kernel(const int* __restrict__ ei, int E) {
    int i = blockIdx.x * blockDim.x + threadIdx.x;
    if (i < E) atomicAdd(&g_deg[ei[E + i]], 1);
}

// Single-kernel exclusive scan (publish + lookback). All blocks publish before
// spinning; 196 tiny blocks are all co-resident -> deadlock-free.
__global__ void scan_rowptr_kernel(int n) {
    __shared__ int sh[256];
    __shared__ int red[256];
    int t = threadIdx.x, b = blockIdx.x;
    int i = b * 256 + t;
    int v = (i < n) ? g_deg[i] : 0;
    sh[t] = v;
    __syncthreads();
    for (int o = 1; o < 256; o <<= 1) {         // Hillis-Steele inclusive
        int u = (t >= o) ? sh[t - o] : 0;
        __syncthreads();
        sh[t] += u;
        __syncthreads();
    }
    if (t == 255) atomicExch(&g_bsum[b], sh[255] + SCAN_FLAG);
    // lookback: lane-parallel poll of all predecessor aggregates
    int agg = 0;
    for (int p = t; p < b; p += 256) {
        int val;
        do { val = *(volatile int*)&g_bsum[p]; } while (val < SCAN_FLAG);
        agg += val - SCAN_FLAG;
    }
    red[t] = agg;
    __syncthreads();
    for (int o = 128; o; o >>= 1) {
        if (t < o) red[t] += red[t + o];
        __syncthreads();
    }
    int excl = red[0] + sh[t] - v;
    if (i < n) {
        g_rowptr[i] = excl;
        g_cursor[i] = excl;
        if (i == n - 1) g_rowptr[n] = excl + v;
    }
}

__global__ void scatter_edges_kernel(const int* __restrict__ ei, int E, int n) {
    int i = blockIdx.x * blockDim.x + threadIdx.x;
    if (i < E) {
        int s = ei[i];
        int d = ei[E + i];
        g_csrsrc[atomicAdd(&g_cursor[d], 1)] = s;
    } else if (i < E + n) {
        int v = i - E;
        g_csrsrc[atomicAdd(&g_cursor[v], 1)] = v;   // self loop
    }
}

// ============================================================================
// PERSISTENT tensor-core GEMM + attention: XL = X @ W via tf32-split mma.sync
// (3 passes), fused a_s/a_d epilogue. Grid = 148 CTAs; each loads W images
// ONCE, then loops over 128-row tiles.
// ============================================================================
constexpr uint32_t SMEM_FLOATS = 128 * XS_STRIDE + 2 * WIMG;   // 51712
constexpr uint32_t SMEM_BYTES  = SMEM_FLOATS * 4;              // 206848

__global__ __launch_bounds__(256) void gemm_mma_kernel(
    const float* __restrict__ X,
    const float* __restrict__ Whi, const float* __restrict__ Wlo,
    const float* __restrict__ atts, const float* __restrict__ attd,
    float* __restrict__ XL, int n)
{
    extern __shared__ float sm[];
    float* Xs = sm;                       // 128 x 132
    float* Wh = sm + 128 * XS_STRIDE;     // 128 x 136
    float* Wl = Wh + WIMG;

    int tid = threadIdx.x, lane = tid & 31, warp = tid >> 5;
    int gid = lane >> 2, tig = lane & 3;

    // W tiles: loaded once per CTA (persistent)
    {
        const float4* gh = (const float4*)Whi;
        const float4* gl = (const float4*)Wlo;
        float4* sh = (float4*)Wh;
        float4* sl = (float4*)Wl;
#pragma unroll
        for (int i = 0; i < 17; i++) {
            int idx = tid + i * 256;
            if (idx < WIMG / 4) { sh[idx] = gh[idx]; sl[idx] = gl[idx]; }
        }
    }

    // att vectors cached in registers (per-thread columns: nt*8 + tig*2 + {0,1})
    float avs[16][2], avd[16][2];
#pragma unroll
    for (int nt = 0; nt < 16; nt++) {
        int col = nt * 8 + tig * 2;
        avs[nt][0] = __ldg(atts + col); avs[nt][1] = __ldg(atts + col + 1);
        avd[nt][0] = __ldg(attd + col); avd[nt][1] = __ldg(attd + col + 1);
    }

    const int rbase = warp * 16;
    int ntiles = (n + 127) >> 7;

    for (int tile = blockIdx.x; tile < ntiles; tile += gridDim.x) {
        int row0 = tile << 7;

        __syncthreads();   // all warps done with previous tile's Xs (and W stores on iter 0)
        // X tile: coalesced float4 loads, padded-stride stores
        {
            const float4* X4 = (const float4*)X;
#pragma unroll
            for (int i = 0; i < 16; i++) {
                int idx = tid + i * 256;        // 128 rows x 32 float4
                int r = idx >> 5, c = idx & 31;
                float4 v = make_float4(0.f, 0.f, 0.f, 0.f);
                if (row0 + r < n) v = X4[(size_t)(row0 + r) * 32 + c];
                *(float4*)(Xs + r * XS_STRIDE + c * 4) = v;
            }
        }
        __syncthreads();

        float c[16][4];
#pragma unroll
        for (int nt = 0; nt < 16; nt++) { c[nt][0] = c[nt][1] = c[nt][2] = c[nt][3] = 0.f; }

        const float* xr0 = Xs + (rbase + gid) * XS_STRIDE + tig;
        const float* xr1 = xr0 + 8 * XS_STRIDE;

        for (int ks = 0; ks < 16; ks++) {
            int k0 = ks * 8;
            float x0 = xr0[k0], x1 = xr1[k0], x2 = xr0[k0 + 4], x3 = xr1[k0 + 4];
            uint32_t ah[4], al[4];
            ah[0] = f2tf32(x0); al[0] = f2tf32(x0 - __uint_as_float(ah[0]));
            ah[1] = f2tf32(x1); al[1] = f2tf32(x1 - __uint_as_float(ah[1]));
            ah[2] = f2tf32(x2); al[2] = f2tf32(x2 - __uint_as_float(ah[2]));
            ah[3] = f2tf32(x3); al[3] = f2tf32(x3 - __uint_as_float(ah[3]));

            const float* wh0 = Wh + (k0 + tig) * WS_STRIDE + gid;
            const float* wl0 = Wl + (k0 + tig) * WS_STRIDE + gid;
#pragma unroll
            for (int nt = 0; nt < 16; nt++) {
                int nb = nt * 8;
                uint32_t bh0 = __float_as_uint(wh0[nb]);
                uint32_t bh1 = __float_as_uint(wh0[nb + 4 * WS_STRIDE]);
                uint32_t bl0 = __float_as_uint(wl0[nb]);
                uint32_t bl1 = __float_as_uint(wl0[nb + 4 * WS_STRIDE]);
                mma_tf32(c[nt], ah, bh0, bh1);
                mma_tf32(c[nt], ah, bl0, bl1);
                mma_tf32(c[nt], al, bh0, bh1);
            }
        }

        // Epilogue: attention dots + fp32 XL stores.
        float ps0 = 0.f, pd0 = 0.f, ps1 = 0.f, pd1 = 0.f;
#pragma unroll
        for (int nt = 0; nt < 16; nt++) {
            ps0 = fmaf(c[nt][0], avs[nt][0], fmaf(c[nt][1], avs[nt][1], ps0));
            pd0 = fmaf(c[nt][0], avd[nt][0], fmaf(c[nt][1], avd[nt][1], pd0));
            ps1 = fmaf(c[nt][2], avs[nt][0], fmaf(c[nt][3], avs[nt][1], ps1));
            pd1 = fmaf(c[nt][2], avd[nt][0], fmaf(c[nt][3], avd[nt][1], pd1));
        }
#pragma unroll
        for (int o = 1; o <= 2; o <<= 1) {
            ps0 += __shfl_xor_sync(0xffffffffu, ps0, o);
            pd0 += __shfl_xor_sync(0xffffffffu, pd0, o);
            ps1 += __shfl_xor_sync(0xffffffffu, ps1, o);
            pd1 += __shfl_xor_sync(0xffffffffu, pd1, o);
        }
        int r0 = row0 + rbase + gid;
        int r1 = r0 + 8;
        if (tig == 0) {
            if (r0 < n) { g_as[r0] = ps0; g_ad[r0] = pd0; }
            if (r1 < n) { g_as[r1] = ps1; g_ad[r1] = pd1; }
        }
        if (r0 < n) {
            float* dst = XL + (size_t)r0 * 128 + tig * 2;
#pragma unroll
            for (int nt = 0; nt < 16; nt++)
                *(float2*)(dst + nt * 8) = make_float2(c[nt][0], c[nt][1]);
        }
        if (r1 < n) {
            float* dst = XL + (size_t)r1 * 128 + tig * 2;
#pragma unroll
            for (int nt = 0; nt < 16; nt++)
                *(float2*)(dst + nt * 8) = make_float2(c[nt][2], c[nt][3]);
        }
    }
}

// ============================================================================
// Aggregation (softmax weight inlined): one warp per dst node.
//   w_e = exp(leakyrelu(a_s[src_e] + a_d[v]))
//   out[v] = relu( (sum_e w_e * XL[src_e]) / (sum_e w_e + 1e-16) + b )
// ============================================================================
__device__ __forceinline__ float edge_w(float as_v, float adv) {
    float t = as_v + adv;
    t = t > 0.f ? t : 0.2f * t;
    return __expf(t);
}

__global__ __launch_bounds__(256) void aggregate_kernel(
    const float* __restrict__ XL, const float* __restrict__ bias,
    float* __restrict__ OUT, int n)
{
    int wid = blockIdx.x * 8 + (threadIdx.x >> 5);
    int lane = threadIdx.x & 31;
    if (wid >= n) return;

    int beg = g_rowptr[wid];
    int end = g_rowptr[wid + 1];
    float adv = g_ad[wid];
    float4 acc = make_float4(0.f, 0.f, 0.f, 0.f);
    float z = 0.f;
    const float4* XL4 = (const float4*)XL;

    int j = beg;
    for (; j + 4 <= end; j += 4) {
        int s0 = g_csrsrc[j],     s1 = g_csrsrc[j + 1];
        int s2 = g_csrsrc[j + 2], s3 = g_csrsrc[j + 3];
        float w0 = edge_w(g_as[s0], adv);
        float w1 = edge_w(g_as[s1], adv);
        float w2 = edge_w(g_as[s2], adv);
        float w3 = edge_w(g_as[s3], adv);
        float4 x0 = XL4[(size_t)s0 * 32 + lane];
        float4 x1 = XL4[(size_t)s1 * 32 + lane];
        float4 x2 = XL4[(size_t)s2 * 32 + lane];
        float4 x3 = XL4[(size_t)s3 * 32 + lane];
        acc.x = fmaf(w0, x0.x, acc.x); acc.y = fmaf(w0, x0.y, acc.y);
        acc.z = fmaf(w0, x0.z, acc.z); acc.w = fmaf(w0, x0.w, acc.w);
        acc.x = fmaf(w1, x1.x, acc.x); acc.y = fmaf(w1, x1.y, acc.y);
        acc.z = fmaf(w1, x1.z, acc.z); acc.w = fmaf(w1, x1.w, acc.w);
        acc.x = fmaf(w2, x2.x, acc.x); acc.y = fmaf(w2, x2.y, acc.y);
        acc.z = fmaf(w2, x2.z, acc.z); acc.w = fmaf(w2, x2.w, acc.w);
        acc.x = fmaf(w3, x3.x, acc.x); acc.y = fmaf(w3, x3.y, acc.y);
        acc.z = fmaf(w3, x3.z, acc.z); acc.w = fmaf(w3, x3.w, acc.w);
        z += (w0 + w1) + (w2 + w3);
    }
    for (; j < end; j++) {
        int s = g_csrsrc[j];
        float w = edge_w(g_as[s], adv);
        float4 xv = XL4[(size_t)s * 32 + lane];
        acc.x = fmaf(w, xv.x, acc.x); acc.y = fmaf(w, xv.y, acc.y);
        acc.z = fmaf(w, xv.z, acc.z); acc.w = fmaf(w, xv.w, acc.w);
        z += w;
    }

    float inv = 1.f / (z + 1e-16f);
    float4 bv = ((const float4*)bias)[lane];
    float4 o;
    o.x = fmaxf(fmaf(acc.x, inv, bv.x), 0.f);
    o.y = fmaxf(fmaf(acc.y, inv, bv.y), 0.f);
    o.z = fmaxf(fmaf(acc.z, inv, bv.z), 0.f);
    o.w = fmaxf(fmaf(acc.w, inv, bv.w), 0.f);
    ((float4*)OUT)[(size_t)wid * 32 + lane] = o;
}

// ============================================================================
// Launch (8 kernels). gemm1 placed 4th (profile slot) — it does not depend on
// scatter, which runs concurrently-ordered after it.
// ============================================================================
extern "C" void kernel_launch(void* const* d_in, const int* in_sizes, int n_in,
                              void* d_out, int out_size)
{
    const float* x   = (const float*)d_in[0];
    const int*   ei  = (const int*)d_in[1];
    const float* W1  = (const float*)d_in[2];
    const float* as1 = (const float*)d_in[3];
    const float* ad1 = (const float*)d_in[4];
    const float* b1  = (const float*)d_in[5];
    const float* W2  = (const float*)d_in[6];
    const float* as2 = (const float*)d_in[7];
    const float* ad2 = (const float*)d_in[8];
    const float* b2  = (const float*)d_in[9];

    int n = in_sizes[0] / DDIM;   // 50000
    int E = in_sizes[1] / 2;      // 800000
    int ee = E + n;
    float* out = (float*)d_out;

    void *xl_p, *h_p, *wh_p, *wl_p;
    cudaGetSymbolAddress(&xl_p, g_xl);
    cudaGetSymbolAddress(&h_p,  g_h);
    cudaGetSymbolAddress(&wh_p, g_whi);
    cudaGetSymbolAddress(&wl_p, g_wlo);
    float* xl = (float*)xl_p;
    float* h  = (float*)h_p;
    const float* whi = (const float*)wh_p;
    const float* wlo = (const float*)wl_p;

    cudaFuncSetAttribute(gemm_mma_kernel, cudaFuncAttributeMaxDynamicSharedMemorySize, SMEM_BYTES);

    int nb = (n + 255) / 256;     // 196

    // --- prep & CSR build (gemm1 interleaved at slot 4 for profiling) ---
    prep_kernel<<<128 + nb, 256>>>(W1, W2, n);
    count_deg_kernel<<<(E + 255) / 256, 256>>>(ei, E);
    scan_rowptr_kernel<<<nb, 256>>>(n);
    gemm_mma_kernel<<<GEMM_GRID, 256, SMEM_BYTES>>>(x, whi, wlo, as1, ad1, xl, n);
    scatter_edges_kernel<<<(ee + 255) / 256, 256>>>(ei, E, n);

    // --- Layer 1 aggregate ---
    aggregate_kernel<<<(n + 7) / 8, 256>>>(xl, b1, h, n);

    // --- Layer 2 ---
    gemm_mma_kernel<<<GEMM_GRID, 256, SMEM_BYTES>>>(h, whi + WIMG, wlo + WIMG, as2, ad2, xl, n);
    aggregate_kernel<<<(n + 7) / 8, 256>>>(xl, b2, out, n);
}

// round 11
// speedup vs baseline: 1.0573x; 1.0011x over previous
#include <cuda_runtime.h>
#include <cstdint>

// Problem constants: N=50000 nodes, E=800000 edges, D=C=128, H=1
#define NMAX 50000
#define EMAX 800000
#define EE   (EMAX + NMAX)
constexpr int DDIM = 128;

constexpr int XS_STRIDE = 132;   // X smem pad: bank = (4*gid + tig) = lane  -> conflict-free
constexpr int WS_STRIDE = 136;   // W smem pad: bank = (8*tig + gid)         -> conflict-free
constexpr int WIMG = 128 * WS_STRIDE;  // 17408 floats per W image
constexpr int SCAN_FLAG = 1 << 30;
constexpr int GEMM_GRID = 148;   // persistent: one CTA per SM

// ---------------- static device scratch ----------------
__device__ float g_xl[(size_t)NMAX * 128];
__device__ float g_h [(size_t)NMAX * 128];
__device__ float g_as[NMAX];
__device__ float g_ad[NMAX];
__device__ int   g_deg[NMAX];
__device__ int   g_rowptr[NMAX + 1];
__device__ int   g_cursor[NMAX];
__device__ int   g_csrsrc[EE];
__device__ int   g_bsum[256];
// W (per layer) as tf32-rounded hi/lo fp32, [k][n] with pad stride WS_STRIDE
__device__ __align__(16) float g_whi[2][WIMG];
__device__ __align__(16) float g_wlo[2][WIMG];

// ---------------- helpers ----------------
__device__ __forceinline__ uint32_t f2tf32(float v) {
    uint32_t u;
    asm("cvt.rna.tf32.f32 %0, %1;" : "=r"(u) : "f"(v));
    return u;
}
__device__ __forceinline__ void mma_tf32(float c[4], const uint32_t a[4], uint32_t b0, uint32_t b1) {
    asm volatile(
        "mma.sync.aligned.m16n8k8.row.col.f32.tf32.tf32.f32 "
        "{%0,%1,%2,%3}, {%4,%5,%6,%7}, {%8,%9}, {%0,%1,%2,%3};"
        : "+f"(c[0]), "+f"(c[1]), "+f"(c[2]), "+f"(c[3])
        : "r"(a[0]), "r"(a[1]), "r"(a[2]), "r"(a[3]), "r"(b0), "r"(b1));
}

// ============================================================================
// Fused prep: blocks [0,128) convert W -> tf32 hi/lo images;
// blocks [128, 128+nb) init g_deg = 1 (self-loop pre-counted); block 128 also
// zeroes g_bsum (scan state).
// ============================================================================
__global__ void prep_kernel(const float* __restrict__ W1, const float* __restrict__ W2, int n) {
    int b = blockIdx.x, t = threadIdx.x;
    if (b < 128) {
        int idx = b * 256 + t;                 // 0..32767
        int layer = idx >> 14;
        int e = idx & 16383;                   // k*128 + n (coalesced read)
        int k = e >> 7, nn = e & 127;
        float v = (layer ? W2 : W1)[e];
        uint32_t hi = f2tf32(v);
        float lo_f = v - __uint_as_float(hi);
        uint32_t lo = f2tf32(lo_f);
        g_whi[layer][k * WS_STRIDE + nn] = __uint_as_float(hi);
        g_wlo[layer][k * WS_STRIDE + nn] = __uint_as_float(lo);
    } else {
        int i = (b - 128) * 256 + t;
        if (i < n) g_deg[i] = 1;               // self loop
        if (b == 128) g_bsum[t] = 0;
    }
}

// ============================================================================
// CSR build
// ============================================================================
__global__ void count_deg_kernel(const int* __restrict__ ei, int E) {
    int i = blockIdx.x * blockDim.x + threadIdx.x;
    if (i < E) atomicAdd(&g_deg[ei[E + i]], 1);
}

// Single-kernel exclusive scan (publish + lookback). All blocks publish before
// spinning; 196 tiny blocks are all co-resident -> deadlock-free.
__global__ void scan_rowptr_kernel(int n) {
    __shared__ int sh[256];
    __shared__ int red[256];
    int t = threadIdx.x, b = blockIdx.x;
    int i = b * 256 + t;
    int v = (i < n) ? g_deg[i] : 0;
    sh[t] = v;
    __syncthreads();
    for (int o = 1; o < 256; o <<= 1) {         // Hillis-Steele inclusive
        int u = (t >= o) ? sh[t - o] : 0;
        __syncthreads();
        sh[t] += u;
        __syncthreads();
    }
    if (t == 255) atomicExch(&g_bsum[b], sh[255] + SCAN_FLAG);
    // lookback: lane-parallel poll of all predecessor aggregates
    int agg = 0;
    for (int p = t; p < b; p += 256) {
        int val;
        do { val = *(volatile int*)&g_bsum[p]; } while (val < SCAN_FLAG);
        agg += val - SCAN_FLAG;
    }
    red[t] = agg;
    __syncthreads();
    for (int o = 128; o; o >>= 1) {
        if (t < o) red[t] += red[t + o];
        __syncthreads();
    }
    int excl = red[0] + sh[t] - v;
    if (i < n) {
        g_rowptr[i] = excl;
        g_cursor[i] = excl;
        if (i == n - 1) g_rowptr[n] = excl + v;
    }
}

__global__ void scatter_edges_kernel(const int* __restrict__ ei, int E, int n) {
    int i = blockIdx.x * blockDim.x + threadIdx.x;
    if (i < E) {
        int s = ei[i];
        int d = ei[E + i];
        g_csrsrc[atomicAdd(&g_cursor[d], 1)] = s;
    } else if (i < E + n) {
        int v = i - E;
        g_csrsrc[atomicAdd(&g_cursor[v], 1)] = v;   // self loop
    }
}

// ============================================================================
// PERSISTENT tensor-core GEMM + attention, 512 threads / 16 warps per CTA.
// N is split across two warp groups: warps 0-7 own cols [0,64), warps 8-15
// own cols [64,128); each warp computes a 16-row x 64-col strip.
// Attention dots combined across the two halves via smem staging.
// ============================================================================
constexpr uint32_t SMEM_FLOATS = 128 * XS_STRIDE + 2 * WIMG + 512;  // +staging
constexpr uint32_t SMEM_BYTES  = SMEM_FLOATS * 4;

__global__ __launch_bounds__(512) void gemm_mma_kernel(
    const float* __restrict__ X,
    const float* __restrict__ Whi, const float* __restrict__ Wlo,
    const float* __restrict__ atts, const float* __restrict__ attd,
    float* __restrict__ XL, int n)
{
    extern __shared__ float sm[];
    float* Xs   = sm;                       // 128 x 132
    float* Wh   = sm + 128 * XS_STRIDE;     // 128 x 136
    float* Wl   = Wh + WIMG;
    float* sh_s = Wl + WIMG;                // [2][128] attention staging
    float* sh_d = sh_s + 256;               // [2][128]

    int tid = threadIdx.x, lane = tid & 31, warp = tid >> 5;
    int gid = lane >> 2, tig = lane & 3;
    int nhalf = warp >> 3;                  // 0: cols 0-63, 1: cols 64-127
    int rbase = (warp & 7) * 16;

    // W tiles: loaded once per CTA (persistent)
    {
        const float4* gh = (const float4*)Whi;
        const float4* gl = (const float4*)Wlo;
        float4* shh = (float4*)Wh;
        float4* sll = (float4*)Wl;
#pragma unroll
        for (int i = 0; i < 9; i++) {
            int idx = tid + i * 512;
            if (idx < WIMG / 4) { shh[idx] = gh[idx]; sll[idx] = gl[idx]; }
        }
    }

    // att vectors cached in registers (this warp's columns: nhalf*64 + nt*8 + tig*2)
    float avs[8][2], avd[8][2];
#pragma unroll
    for (int nt = 0; nt < 8; nt++) {
        int col = nhalf * 64 + nt * 8 + tig * 2;
        avs[nt][0] = __ldg(atts + col); avs[nt][1] = __ldg(atts + col + 1);
        avd[nt][0] = __ldg(attd + col); avd[nt][1] = __ldg(attd + col + 1);
    }

    int ntiles = (n + 127) >> 7;

    for (int tile = blockIdx.x; tile < ntiles; tile += gridDim.x) {
        int row0 = tile << 7;

        __syncthreads();   // prev tile fully consumed (Xs + staging); W stores on iter 0
        // X tile: coalesced float4 loads, padded-stride stores
        {
            const float4* X4 = (const float4*)X;
#pragma unroll
            for (int i = 0; i < 8; i++) {
                int idx = tid + i * 512;        // 128 rows x 32 float4
                int r = idx >> 5, c = idx & 31;
                float4 v = make_float4(0.f, 0.f, 0.f, 0.f);
                if (row0 + r < n) v = X4[(size_t)(row0 + r) * 32 + c];
                *(float4*)(Xs + r * XS_STRIDE + c * 4) = v;
            }
        }
        __syncthreads();

        float c[8][4];
#pragma unroll
        for (int nt = 0; nt < 8; nt++) { c[nt][0] = c[nt][1] = c[nt][2] = c[nt][3] = 0.f; }

        const float* xr0 = Xs + (rbase + gid) * XS_STRIDE + tig;
        const float* xr1 = xr0 + 8 * XS_STRIDE;

        for (int ks = 0; ks < 16; ks++) {
            int k0 = ks * 8;
            float x0 = xr0[k0], x1 = xr1[k0], x2 = xr0[k0 + 4], x3 = xr1[k0 + 4];
            uint32_t ah[4], al[4];
            ah[0] = f2tf32(x0); al[0] = f2tf32(x0 - __uint_as_float(ah[0]));
            ah[1] = f2tf32(x1); al[1] = f2tf32(x1 - __uint_as_float(ah[1]));
            ah[2] = f2tf32(x2); al[2] = f2tf32(x2 - __uint_as_float(ah[2]));
            ah[3] = f2tf32(x3); al[3] = f2tf32(x3 - __uint_as_float(ah[3]));

            const float* wh0 = Wh + (k0 + tig) * WS_STRIDE + nhalf * 64 + gid;
            const float* wl0 = Wl + (k0 + tig) * WS_STRIDE + nhalf * 64 + gid;
#pragma unroll
            for (int nt = 0; nt < 8; nt++) {
                int nb = nt * 8;
                uint32_t bh0 = __float_as_uint(wh0[nb]);
                uint32_t bh1 = __float_as_uint(wh0[nb + 4 * WS_STRIDE]);
                uint32_t bl0 = __float_as_uint(wl0[nb]);
                uint32_t bl1 = __float_as_uint(wl0[nb + 4 * WS_STRIDE]);
                mma_tf32(c[nt], ah, bh0, bh1);
                mma_tf32(c[nt], ah, bl0, bl1);
                mma_tf32(c[nt], al, bh0, bh1);
            }
        }

        // Epilogue: per-half attention dots -> smem staging; XL stores.
        float ps0 = 0.f, pd0 = 0.f, ps1 = 0.f, pd1 = 0.f;
#pragma unroll
        for (int nt = 0; nt < 8; nt++) {
            ps0 = fmaf(c[nt][0], avs[nt][0], fmaf(c[nt][1], avs[nt][1], ps0));
            pd0 = fmaf(c[nt][0], avd[nt][0], fmaf(c[nt][1], avd[nt][1], pd0));
            ps1 = fmaf(c[nt][2], avs[nt][0], fmaf(c[nt][3], avs[nt][1], ps1));
            pd1 = fmaf(c[nt][2], avd[nt][0], fmaf(c[nt][3], avd[nt][1], pd1));
        }
#pragma unroll
        for (int o = 1; o <= 2; o <<= 1) {
            ps0 += __shfl_xor_sync(0xffffffffu, ps0, o);
            pd0 += __shfl_xor_sync(0xffffffffu, pd0, o);
            ps1 += __shfl_xor_sync(0xffffffffu, ps1, o);
            pd1 += __shfl_xor_sync(0xffffffffu, pd1, o);
        }
        if (tig == 0) {
            sh_s[nhalf * 128 + rbase + gid]     = ps0;
            sh_d[nhalf * 128 + rbase + gid]     = pd0;
            sh_s[nhalf * 128 + rbase + gid + 8] = ps1;
            sh_d[nhalf * 128 + rbase + gid + 8] = pd1;
        }

        int r0 = row0 + rbase + gid;
        int r1 = r0 + 8;
        if (r0 < n) {
            float* dst = XL + (size_t)r0 * 128 + nhalf * 64 + tig * 2;
#pragma unroll
            for (int nt = 0; nt < 8; nt++)
                *(float2*)(dst + nt * 8) = make_float2(c[nt][0], c[nt][1]);
        }
        if (r1 < n) {
            float* dst = XL + (size_t)r1 * 128 + nhalf * 64 + tig * 2;
#pragma unroll
            for (int nt = 0; nt < 8; nt++)
                *(float2*)(dst + nt * 8) = make_float2(c[nt][2], c[nt][3]);
        }

        __syncthreads();   // staging complete
        if (tid < 128) {
            int r = row0 + tid;
            if (r < n) {
                g_as[r] = sh_s[tid] + sh_s[128 + tid];
                g_ad[r] = sh_d[tid] + sh_d[128 + tid];
            }
        }
    }
}

// ============================================================================
// Aggregation (softmax weight inlined): one warp per dst node.
//   w_e = exp(leakyrelu(a_s[src_e] + a_d[v]))
//   out[v] = relu( (sum_e w_e * XL[src_e]) / (sum_e w_e + 1e-16) + b )
// ============================================================================
__device__ __forceinline__ float edge_w(float as_v, float adv) {
    float t = as_v + adv;
    t = t > 0.f ? t : 0.2f * t;
    return __expf(t);
}

__global__ __launch_bounds__(256) void aggregate_kernel(
    const float* __restrict__ XL, const float* __restrict__ bias,
    float* __restrict__ OUT, int n)
{
    int wid = blockIdx.x * 8 + (threadIdx.x >> 5);
    int lane = threadIdx.x & 31;
    if (wid >= n) return;

    int beg = g_rowptr[wid];
    int end = g_rowptr[wid + 1];
    float adv = g_ad[wid];
    float4 acc = make_float4(0.f, 0.f, 0.f, 0.f);
    float z = 0.f;
    const float4* XL4 = (const float4*)XL;

    int j = beg;
    for (; j + 4 <= end; j += 4) {
        int s0 = g_csrsrc[j],     s1 = g_csrsrc[j + 1];
        int s2 = g_csrsrc[j + 2], s3 = g_csrsrc[j + 3];
        float w0 = edge_w(g_as[s0], adv);
        float w1 = edge_w(g_as[s1], adv);
        float w2 = edge_w(g_as[s2], adv);
        float w3 = edge_w(g_as[s3], adv);
        float4 x0 = XL4[(size_t)s0 * 32 + lane];
        float4 x1 = XL4[(size_t)s1 * 32 + lane];
        float4 x2 = XL4[(size_t)s2 * 32 + lane];
        float4 x3 = XL4[(size_t)s3 * 32 + lane];
        acc.x = fmaf(w0, x0.x, acc.x); acc.y = fmaf(w0, x0.y, acc.y);
        acc.z = fmaf(w0, x0.z, acc.z); acc.w = fmaf(w0, x0.w, acc.w);
        acc.x = fmaf(w1, x1.x, acc.x); acc.y = fmaf(w1, x1.y, acc.y);
        acc.z = fmaf(w1, x1.z, acc.z); acc.w = fmaf(w1, x1.w, acc.w);
        acc.x = fmaf(w2, x2.x, acc.x); acc.y = fmaf(w2, x2.y, acc.y);
        acc.z = fmaf(w2, x2.z, acc.z); acc.w = fmaf(w2, x2.w, acc.w);
        acc.x = fmaf(w3, x3.x, acc.x); acc.y = fmaf(w3, x3.y, acc.y);
        acc.z = fmaf(w3, x3.z, acc.z); acc.w = fmaf(w3, x3.w, acc.w);
        z += (w0 + w1) + (w2 + w3);
    }
    for (; j < end; j++) {
        int s = g_csrsrc[j];
        float w = edge_w(g_as[s], adv);
        float4 xv = XL4[(size_t)s * 32 + lane];
        acc.x = fmaf(w, xv.x, acc.x); acc.y = fmaf(w, xv.y, acc.y);
        acc.z = fmaf(w, xv.z, acc.z); acc.w = fmaf(w, xv.w, acc.w);
        z += w;
    }

    float inv = 1.f / (z + 1e-16f);
    float4 bv = ((const float4*)bias)[lane];
    float4 o;
    o.x = fmaxf(fmaf(acc.x, inv, bv.x), 0.f);
    o.y = fmaxf(fmaf(acc.y, inv, bv.y), 0.f);
    o.z = fmaxf(fmaf(acc.z, inv, bv.z), 0.f);
    o.w = fmaxf(fmaf(acc.w, inv, bv.w), 0.f);
    ((float4*)OUT)[(size_t)wid * 32 + lane] = o;
}

// ============================================================================
// Launch (8 kernels). gemm1 kept at slot 4 (the profiled slot).
// ============================================================================
extern "C" void kernel_launch(void* const* d_in, const int* in_sizes, int n_in,
                              void* d_out, int out_size)
{
    const float* x   = (const float*)d_in[0];
    const int*   ei  = (const int*)d_in[1];
    const float* W1  = (const float*)d_in[2];
    const float* as1 = (const float*)d_in[3];
    const float* ad1 = (const float*)d_in[4];
    const float* b1  = (const float*)d_in[5];
    const float* W2  = (const float*)d_in[6];
    const float* as2 = (const float*)d_in[7];
    const float* ad2 = (const float*)d_in[8];
    const float* b2  = (const float*)d_in[9];

    int n = in_sizes[0] / DDIM;   // 50000
    int E = in_sizes[1] / 2;      // 800000
    int ee = E + n;
    float* out = (float*)d_out;

    void *xl_p, *h_p, *wh_p, *wl_p;
    cudaGetSymbolAddress(&xl_p, g_xl);
    cudaGetSymbolAddress(&h_p,  g_h);
    cudaGetSymbolAddress(&wh_p, g_whi);
    cudaGetSymbolAddress(&wl_p, g_wlo);
    float* xl = (float*)xl_p;
    float* h  = (float*)h_p;
    const float* whi = (const float*)wh_p;
    const float* wlo = (const float*)wl_p;

    cudaFuncSetAttribute(gemm_mma_kernel, cudaFuncAttributeMaxDynamicSharedMemorySize, SMEM_BYTES);

    int nb = (n + 255) / 256;     // 196

    // --- prep & CSR build (gemm1 at slot 4 for profiling) ---
    prep_kernel<<<128 + nb, 256>>>(W1, W2, n);
    count_deg_kernel<<<(E + 255) / 256, 256>>>(ei, E);
    scan_rowptr_kernel<<<nb, 256>>>(n);
    gemm_mma_kernel<<<GEMM_GRID, 512, SMEM_BYTES>>>(x, whi, wlo, as1, ad1, xl, n);
    scatter_edges_kernel<<<(ee + 255) / 256, 256>>>(ei, E, n);

    // --- Layer 1 aggregate ---
    aggregate_kernel<<<(n + 7) / 8, 256>>>(xl, b1, h, n);

    // --- Layer 2 ---
    gemm_mma_kernel<<<GEMM_GRID, 512, SMEM_BYTES>>>(h, whi + WIMG, wlo + WIMG, as2, ad2, xl, n);
    aggregate_kernel<<<(n + 7) / 8, 256>>>(xl, b2, out, n);
}

// round 12
// speedup vs baseline: 1.2269x; 1.1605x over previous
#include <cuda_runtime.h>
#include <cuda_bf16.h>
#include <cstdint>

// Problem constants: N=50000 nodes, E=800000 edges, D=C=128, H=1
#define NMAX 50000
#define EMAX 800000
#define EE   (EMAX + NMAX)
constexpr int DDIM = 128;
constexpr int SCAN_FLAG = 1 << 30;
constexpr int GEMM_GRID = 148;     // persistent: one CTA per SM

// bf16 tile layout: 136 bf16 per row (pad) = 68 32-bit words; bank = 4*gid+tig
constexpr int RW = 68;             // words per row
constexpr int IMG_W = 128 * RW;    // 8704 words per 128-row bf16 image
constexpr int IMG_F4 = IMG_W / 4;  // 2176 float4 per image

// ---------------- static device scratch ----------------
__device__ float g_xl[(size_t)NMAX * 128];
__device__ float g_h [(size_t)NMAX * 128];
__device__ float g_as[NMAX];
__device__ float g_ad[NMAX];
__device__ int   g_deg[NMAX];
__device__ int   g_rowptr[NMAX + 1];
__device__ int   g_cursor[NMAX];
__device__ int   g_csrsrc[EE];
__device__ int   g_bsum[256];
// W per layer, TRANSPOSED [n][k], bf16 hi/lo, padded rows (136 bf16)
__device__ __align__(16) __nv_bfloat16 g_wbh[2][128 * 136];
__device__ __align__(16) __nv_bfloat16 g_wbl[2][128 * 136];

// ---------------- helpers ----------------
__device__ __forceinline__ void cvt_hi_lo(float a, float b, uint32_t& hi, uint32_t& lo) {
    __nv_bfloat16 ha = __float2bfloat16_rn(a), hb = __float2bfloat16_rn(b);
    float ra = a - __bfloat162float(ha), rb = b - __bfloat162float(hb);
    __nv_bfloat16 la = __float2bfloat16_rn(ra), lb = __float2bfloat16_rn(rb);
    hi = ((uint32_t)(*(unsigned short*)&hb) << 16) | (*(unsigned short*)&ha);
    lo = ((uint32_t)(*(unsigned short*)&lb) << 16) | (*(unsigned short*)&la);
}
__device__ __forceinline__ void mma_bf16(float c[4], const uint32_t a[4], uint32_t b0, uint32_t b1) {
    asm volatile(
        "mma.sync.aligned.m16n8k16.row.col.f32.bf16.bf16.f32 "
        "{%0,%1,%2,%3}, {%4,%5,%6,%7}, {%8,%9}, {%0,%1,%2,%3};"
        : "+f"(c[0]), "+f"(c[1]), "+f"(c[2]), "+f"(c[3])
        : "r"(a[0]), "r"(a[1]), "r"(a[2]), "r"(a[3]), "r"(b0), "r"(b1));
}

// ============================================================================
// Fused prep: blocks [0,128) build W^T bf16 hi/lo images; blocks [128,128+nb)
// init g_deg = 1 (self loop pre-counted); block 128 zeroes scan state.
// ============================================================================
__global__ void prep_kernel(const float* __restrict__ W1, const float* __restrict__ W2, int n) {
    int b = blockIdx.x, t = threadIdx.x;
    if (b < 128) {
        int idx = b * 256 + t;                 // 0..32767
        int layer = idx >> 14;
        int e = idx & 16383;
        int nn = e >> 7, k = e & 127;          // write coalesced in k
        float v = (layer ? W2 : W1)[k * 128 + nn];
        __nv_bfloat16 h = __float2bfloat16_rn(v);
        float r = v - __bfloat162float(h);
        g_wbh[layer][nn * 136 + k] = h;
        g_wbl[layer][nn * 136 + k] = __float2bfloat16_rn(r);
    } else {
        int i = (b - 128) * 256 + t;
        if (i < n) g_deg[i] = 1;               // self loop
        if (b == 128) g_bsum[t] = 0;
    }
}

// ============================================================================
// CSR build
// ============================================================================
__global__ void count_deg_kernel(const int* __restrict__ ei, int E) {
    int i = blockIdx.x * blockDim.x + threadIdx.x;
    if (i < E) atomicAdd(&g_deg[ei[E + i]], 1);
}

__global__ void scan_rowptr_kernel(int n) {
    __shared__ int sh[256];
    __shared__ int red[256];
    int t = threadIdx.x, b = blockIdx.x;
    int i = b * 256 + t;
    int v = (i < n) ? g_deg[i] : 0;
    sh[t] = v;
    __syncthreads();
    for (int o = 1; o < 256; o <<= 1) {
        int u = (t >= o) ? sh[t - o] : 0;
        __syncthreads();
        sh[t] += u;
        __syncthreads();
    }
    if (t == 255) atomicExch(&g_bsum[b], sh[255] + SCAN_FLAG);
    int agg = 0;
    for (int p = t; p < b; p += 256) {
        int val;
        do { val = *(volatile int*)&g_bsum[p]; } while (val < SCAN_FLAG);
        agg += val - SCAN_FLAG;
    }
    red[t] = agg;
    __syncthreads();
    for (int o = 128; o; o >>= 1) {
        if (t < o) red[t] += red[t + o];
        __syncthreads();
    }
    int excl = red[0] + sh[t] - v;
    if (i < n) {
        g_rowptr[i] = excl;
        g_cursor[i] = excl;
        if (i == n - 1) g_rowptr[n] = excl + v;
    }
}

__global__ void scatter_edges_kernel(const int* __restrict__ ei, int E, int n) {
    int i = blockIdx.x * blockDim.x + threadIdx.x;
    if (i < E) {
        int s = ei[i];
        int d = ei[E + i];
        g_csrsrc[atomicAdd(&g_cursor[d], 1)] = s;
    } else if (i < E + n) {
        int v = i - E;
        g_csrsrc[atomicAdd(&g_cursor[v], 1)] = v;   // self loop
    }
}

// ============================================================================
// PERSISTENT bf16-split GEMM + attention. 256 threads / 8 warps per CTA.
// warp w: col half = w>>2 (64 cols), rows = (w&3)*32 .. +31 (two m16 groups).
// 3 passes per mma slot: ah*bh + ah*bl + al*bh (lo*lo dropped, ~2^-16).
// ============================================================================
constexpr uint32_t SMEM_WORDS = 4 * IMG_W + 512;     // Xh|Xl|Bh|Bl + staging
constexpr uint32_t SMEM_BYTES = SMEM_WORDS * 4;      // 141312

__global__ __launch_bounds__(256) void gemm_mma_kernel(
    const float* __restrict__ X,
    const float4* __restrict__ Wbh_g, const float4* __restrict__ Wbl_g,
    const float* __restrict__ atts, const float* __restrict__ attd,
    float* __restrict__ XL, int n)
{
    extern __shared__ uint32_t smu[];
    uint32_t* Xh = smu;
    uint32_t* Xl = smu + IMG_W;
    uint32_t* Bh = smu + 2 * IMG_W;
    uint32_t* Bl = smu + 3 * IMG_W;
    float* sh_s = (float*)(smu + 4 * IMG_W);   // [2][128]
    float* sh_d = sh_s + 256;

    int tid = threadIdx.x, lane = tid & 31, warp = tid >> 5;
    int gid = lane >> 2, tig = lane & 3;
    int nhalf = warp >> 2;
    int rbase = (warp & 3) * 32;

    // W images: copied once per CTA (persistent)
    {
        float4* dh = (float4*)Bh;
        float4* dl = (float4*)Bl;
#pragma unroll
        for (int i = 0; i < 9; i++) {
            int idx = tid + i * 256;
            if (idx < IMG_F4) { dh[idx] = Wbh_g[idx]; dl[idx] = Wbl_g[idx]; }
        }
    }

    // att vectors in registers (cols: nhalf*64 + nt*8 + tig*2 + {0,1})
    float avs[8][2], avd[8][2];
#pragma unroll
    for (int nt = 0; nt < 8; nt++) {
        int col = nhalf * 64 + nt * 8 + tig * 2;
        avs[nt][0] = __ldg(atts + col); avs[nt][1] = __ldg(atts + col + 1);
        avd[nt][0] = __ldg(attd + col); avd[nt][1] = __ldg(attd + col + 1);
    }

    int ntiles = (n + 127) >> 7;

    for (int tile = blockIdx.x; tile < ntiles; tile += gridDim.x) {
        int row0 = tile << 7;

        __syncthreads();   // prev tile fully consumed; W copy on first iter
        // X tile: fp32 loads, bf16 hi/lo split, padded stores (uint2 = 2 words)
        {
            const float4* X4 = (const float4*)X;
#pragma unroll
            for (int i = 0; i < 16; i++) {
                int idx = tid + i * 256;        // 128 rows x 32 float4
                int r = idx >> 5, cc = idx & 31;
                float4 v = make_float4(0.f, 0.f, 0.f, 0.f);
                if (row0 + r < n) v = X4[(size_t)(row0 + r) * 32 + cc];
                uint32_t h0, l0, h1, l1;
                cvt_hi_lo(v.x, v.y, h0, l0);
                cvt_hi_lo(v.z, v.w, h1, l1);
                int w = r * RW + cc * 2;
                *(uint2*)(Xh + w) = make_uint2(h0, h1);
                *(uint2*)(Xl + w) = make_uint2(l0, l1);
            }
        }
        __syncthreads();

        float c[2][8][4];
#pragma unroll
        for (int g = 0; g < 2; g++)
#pragma unroll
            for (int nt = 0; nt < 8; nt++)
                c[g][nt][0] = c[g][nt][1] = c[g][nt][2] = c[g][nt][3] = 0.f;

        int aro = (rbase + gid) * RW + tig;                    // A row base
        int bro = (nhalf * 64 + gid) * RW + tig;               // B row base

#pragma unroll
        for (int ks = 0; ks < 8; ks++) {
            int kw = ks * 8;
            uint32_t ah[2][4], al[2][4];
#pragma unroll
            for (int g = 0; g < 2; g++) {
                int o = aro + g * (16 * RW) + kw;
                ah[g][0] = Xh[o];            al[g][0] = Xl[o];
                ah[g][1] = Xh[o + 8 * RW];   al[g][1] = Xl[o + 8 * RW];
                ah[g][2] = Xh[o + 4];        al[g][2] = Xl[o + 4];
                ah[g][3] = Xh[o + 8 * RW + 4]; al[g][3] = Xl[o + 8 * RW + 4];
            }
#pragma unroll
            for (int nt = 0; nt < 8; nt++) {
                int o = bro + nt * (8 * RW) + kw;
                uint32_t bh0 = Bh[o], bh1 = Bh[o + 4];
                uint32_t bl0 = Bl[o], bl1 = Bl[o + 4];
                mma_bf16(c[0][nt], ah[0], bh0, bh1);
                mma_bf16(c[0][nt], ah[0], bl0, bl1);
                mma_bf16(c[0][nt], al[0], bh0, bh1);
                mma_bf16(c[1][nt], ah[1], bh0, bh1);
                mma_bf16(c[1][nt], ah[1], bl0, bl1);
                mma_bf16(c[1][nt], al[1], bh0, bh1);
            }
        }

        // Epilogue: per-half attention dots -> staging; fp32 XL stores.
#pragma unroll
        for (int g = 0; g < 2; g++) {
            float ps0 = 0.f, pd0 = 0.f, ps1 = 0.f, pd1 = 0.f;
#pragma unroll
            for (int nt = 0; nt < 8; nt++) {
                ps0 = fmaf(c[g][nt][0], avs[nt][0], fmaf(c[g][nt][1], avs[nt][1], ps0));
                pd0 = fmaf(c[g][nt][0], avd[nt][0], fmaf(c[g][nt][1], avd[nt][1], pd0));
                ps1 = fmaf(c[g][nt][2], avs[nt][0], fmaf(c[g][nt][3], avs[nt][1], ps1));
                pd1 = fmaf(c[g][nt][2], avd[nt][0], fmaf(c[g][nt][3], avd[nt][1], pd1));
            }
#pragma unroll
            for (int o = 1; o <= 2; o <<= 1) {
                ps0 += __shfl_xor_sync(0xffffffffu, ps0, o);
                pd0 += __shfl_xor_sync(0xffffffffu, pd0, o);
                ps1 += __shfl_xor_sync(0xffffffffu, ps1, o);
                pd1 += __shfl_xor_sync(0xffffffffu, pd1, o);
            }
            int rloc = rbase + g * 16 + gid;
            if (tig == 0) {
                sh_s[nhalf * 128 + rloc]     = ps0;
                sh_d[nhalf * 128 + rloc]     = pd0;
                sh_s[nhalf * 128 + rloc + 8] = ps1;
                sh_d[nhalf * 128 + rloc + 8] = pd1;
            }
            int r0 = row0 + rloc;
            int r1 = r0 + 8;
            if (r0 < n) {
                float* dst = XL + (size_t)r0 * 128 + nhalf * 64 + tig * 2;
#pragma unroll
                for (int nt = 0; nt < 8; nt++)
                    *(float2*)(dst + nt * 8) = make_float2(c[g][nt][0], c[g][nt][1]);
            }
            if (r1 < n) {
                float* dst = XL + (size_t)r1 * 128 + nhalf * 64 + tig * 2;
#pragma unroll
                for (int nt = 0; nt < 8; nt++)
                    *(float2*)(dst + nt * 8) = make_float2(c[g][nt][2], c[g][nt][3]);
            }
        }

        __syncthreads();   // staging complete
        if (tid < 128) {
            int r = row0 + tid;
            if (r < n) {
                g_as[r] = sh_s[tid] + sh_s[128 + tid];
                g_ad[r] = sh_d[tid] + sh_d[128 + tid];
            }
        }
    }
}

// ============================================================================
// Aggregation (softmax weight inlined): one warp per dst node.
// ============================================================================
__device__ __forceinline__ float edge_w(float as_v, float adv) {
    float t = as_v + adv;
    t = t > 0.f ? t : 0.2f * t;
    return __expf(t);
}

__global__ __launch_bounds__(256) void aggregate_kernel(
    const float* __restrict__ XL, const float* __restrict__ bias,
    float* __restrict__ OUT, int n)
{
    int wid = blockIdx.x * 8 + (threadIdx.x >> 5);
    int lane = threadIdx.x & 31;
    if (wid >= n) return;

    int beg = g_rowptr[wid];
    int end = g_rowptr[wid + 1];
    float adv = g_ad[wid];
    float4 acc = make_float4(0.f, 0.f, 0.f, 0.f);
    float z = 0.f;
    const float4* XL4 = (const float4*)XL;

    int j = beg;
    for (; j + 4 <= end; j += 4) {
        int s0 = g_csrsrc[j],     s1 = g_csrsrc[j + 1];
        int s2 = g_csrsrc[j + 2], s3 = g_csrsrc[j + 3];
        float w0 = edge_w(g_as[s0], adv);
        float w1 = edge_w(g_as[s1], adv);
        float w2 = edge_w(g_as[s2], adv);
        float w3 = edge_w(g_as[s3], adv);
        float4 x0 = XL4[(size_t)s0 * 32 + lane];
        float4 x1 = XL4[(size_t)s1 * 32 + lane];
        float4 x2 = XL4[(size_t)s2 * 32 + lane];
        float4 x3 = XL4[(size_t)s3 * 32 + lane];
        acc.x = fmaf(w0, x0.x, acc.x); acc.y = fmaf(w0, x0.y, acc.y);
        acc.z = fmaf(w0, x0.z, acc.z); acc.w = fmaf(w0, x0.w, acc.w);
        acc.x = fmaf(w1, x1.x, acc.x); acc.y = fmaf(w1, x1.y, acc.y);
        acc.z = fmaf(w1, x1.z, acc.z); acc.w = fmaf(w1, x1.w, acc.w);
        acc.x = fmaf(w2, x2.x, acc.x); acc.y = fmaf(w2, x2.y, acc.y);
        acc.z = fmaf(w2, x2.z, acc.z); acc.w = fmaf(w2, x2.w, acc.w);
        acc.x = fmaf(w3, x3.x, acc.x); acc.y = fmaf(w3, x3.y, acc.y);
        acc.z = fmaf(w3, x3.z, acc.z); acc.w = fmaf(w3, x3.w, acc.w);
        z += (w0 + w1) + (w2 + w3);
    }
    for (; j < end; j++) {
        int s = g_csrsrc[j];
        float w = edge_w(g_as[s], adv);
        float4 xv = XL4[(size_t)s * 32 + lane];
        acc.x = fmaf(w, xv.x, acc.x); acc.y = fmaf(w, xv.y, acc.y);
        acc.z = fmaf(w, xv.z, acc.z); acc.w = fmaf(w, xv.w, acc.w);
        z += w;
    }

    float inv = 1.f / (z + 1e-16f);
    float4 bv = ((const float4*)bias)[lane];
    float4 o;
    o.x = fmaxf(fmaf(acc.x, inv, bv.x), 0.f);
    o.y = fmaxf(fmaf(acc.y, inv, bv.y), 0.f);
    o.z = fmaxf(fmaf(acc.z, inv, bv.z), 0.f);
    o.w = fmaxf(fmaf(acc.w, inv, bv.w), 0.f);
    ((float4*)OUT)[(size_t)wid * 32 + lane] = o;
}

// ============================================================================
// Launch (8 kernels). gemm1 kept at slot 4 (the profiled slot).
// ============================================================================
extern "C" void kernel_launch(void* const* d_in, const int* in_sizes, int n_in,
                              void* d_out, int out_size)
{
    const float* x   = (const float*)d_in[0];
    const int*   ei  = (const int*)d_in[1];
    const float* W1  = (const float*)d_in[2];
    const float* as1 = (const float*)d_in[3];
    const float* ad1 = (const float*)d_in[4];
    const float* b1  = (const float*)d_in[5];
    const float* W2  = (const float*)d_in[6];
    const float* as2 = (const float*)d_in[7];
    const float* ad2 = (const float*)d_in[8];
    const float* b2  = (const float*)d_in[9];

    int n = in_sizes[0] / DDIM;   // 50000
    int E = in_sizes[1] / 2;      // 800000
    int ee = E + n;
    float* out = (float*)d_out;

    void *xl_p, *h_p, *wh_p, *wl_p;
    cudaGetSymbolAddress(&xl_p, g_xl);
    cudaGetSymbolAddress(&h_p,  g_h);
    cudaGetSymbolAddress(&wh_p, g_wbh);
    cudaGetSymbolAddress(&wl_p, g_wbl);
    float* xl = (float*)xl_p;
    float* h  = (float*)h_p;
    const __nv_bfloat16* wbh = (const __nv_bfloat16*)wh_p;
    const __nv_bfloat16* wbl = (const __nv_bfloat16*)wl_p;

    cudaFuncSetAttribute(gemm_mma_kernel, cudaFuncAttributeMaxDynamicSharedMemorySize, SMEM_BYTES);

    int nb = (n + 255) / 256;     // 196

    // --- prep & CSR build (gemm1 at slot 4 for profiling) ---
    prep_kernel<<<128 + nb, 256>>>(W1, W2, n);
    count_deg_kernel<<<(E + 255) / 256, 256>>>(ei, E);
    scan_rowptr_kernel<<<nb, 256>>>(n);
    gemm_mma_kernel<<<GEMM_GRID, 256, SMEM_BYTES>>>(
        x, (const float4*)wbh, (const float4*)wbl, as1, ad1, xl, n);
    scatter_edges_kernel<<<(ee + 255) / 256, 256>>>(ei, E, n);

    // --- Layer 1 aggregate ---
    aggregate_kernel<<<(n + 7) / 8, 256>>>(xl, b1, h, n);

    // --- Layer 2 ---
    gemm_mma_kernel<<<GEMM_GRID, 256, SMEM_BYTES>>>(
        h, (const float4*)(wbh + 128 * 136), (const float4*)(wbl + 128 * 136),
        as2, ad2, xl, n);
    aggregate_kernel<<<(n + 7) / 8, 256>>>(xl, b2, out, n);
}

// round 13
// speedup vs baseline: 1.2430x; 1.0131x over previous
#include <cuda_runtime.h>
#include <cuda_bf16.h>
#include <cstdint>

// Problem constants: N=50000 nodes, E=800000 edges, D=C=128, H=1
#define NMAX 50000
#define EMAX 800000
#define EE   (EMAX + NMAX)
constexpr int DDIM = 128;
constexpr int SCAN_FLAG = 1 << 30;
constexpr int GEMM_GRID = 148;     // persistent: one CTA per SM

// bf16 tile layout: 136 bf16 per row (pad) = 68 32-bit words; bank = 4*gid+tig
constexpr int RW = 68;             // words per row
constexpr int IMG_W = 128 * RW;    // 8704 words per 128-row bf16 image
constexpr int IMG_F4 = IMG_W / 4;  // 2176 float4 per image

// ---------------- static device scratch ----------------
__device__ float g_xl[(size_t)NMAX * 128];
__device__ float g_h [(size_t)NMAX * 128];
__device__ float g_as[NMAX];
__device__ float g_ad[NMAX];
__device__ int   g_deg[NMAX];
__device__ int   g_rowptr[NMAX + 1];
__device__ int   g_cursor[NMAX];
__device__ int   g_csrsrc[EE];
__device__ int   g_bsum[256];
// W per layer, TRANSPOSED [n][k], bf16 hi/lo, padded rows (136 bf16)
__device__ __align__(16) __nv_bfloat16 g_wbh[2][128 * 136];
__device__ __align__(16) __nv_bfloat16 g_wbl[2][128 * 136];

// ---------------- helpers ----------------
__device__ __forceinline__ void cvt_hi_lo(float a, float b, uint32_t& hi, uint32_t& lo) {
    __nv_bfloat16 ha = __float2bfloat16_rn(a), hb = __float2bfloat16_rn(b);
    float ra = a - __bfloat162float(ha), rb = b - __bfloat162float(hb);
    __nv_bfloat16 la = __float2bfloat16_rn(ra), lb = __float2bfloat16_rn(rb);
    hi = ((uint32_t)(*(unsigned short*)&hb) << 16) | (*(unsigned short*)&ha);
    lo = ((uint32_t)(*(unsigned short*)&lb) << 16) | (*(unsigned short*)&la);
}
__device__ __forceinline__ void mma_bf16(float c[4], const uint32_t a[4], uint32_t b0, uint32_t b1) {
    asm volatile(
        "mma.sync.aligned.m16n8k16.row.col.f32.bf16.bf16.f32 "
        "{%0,%1,%2,%3}, {%4,%5,%6,%7}, {%8,%9}, {%0,%1,%2,%3};"
        : "+f"(c[0]), "+f"(c[1]), "+f"(c[2]), "+f"(c[3])
        : "r"(a[0]), "r"(a[1]), "r"(a[2]), "r"(a[3]), "r"(b0), "r"(b1));
}

// ============================================================================
// Fused prep: blocks [0,128) build W^T bf16 hi/lo images; blocks [128,128+nb)
// init g_deg = 1 (self loop pre-counted); block 128 zeroes scan state.
// ============================================================================
__global__ void prep_kernel(const float* __restrict__ W1, const float* __restrict__ W2, int n) {
    int b = blockIdx.x, t = threadIdx.x;
    if (b < 128) {
        int idx = b * 256 + t;                 // 0..32767
        int layer = idx >> 14;
        int e = idx & 16383;
        int nn = e >> 7, k = e & 127;          // write coalesced in k
        float v = (layer ? W2 : W1)[k * 128 + nn];
        __nv_bfloat16 h = __float2bfloat16_rn(v);
        float r = v - __bfloat162float(h);
        g_wbh[layer][nn * 136 + k] = h;
        g_wbl[layer][nn * 136 + k] = __float2bfloat16_rn(r);
    } else {
        int i = (b - 128) * 256 + t;
        if (i < n) g_deg[i] = 1;               // self loop
        if (b == 128) g_bsum[t] = 0;
    }
}

// ============================================================================
// CSR build
// ============================================================================
__global__ void count_deg_kernel(const int* __restrict__ ei, int E) {
    int i = blockIdx.x * blockDim.x + threadIdx.x;
    if (i < E) atomicAdd(&g_deg[ei[E + i]], 1);
}

__global__ void scan_rowptr_kernel(int n) {
    __shared__ int sh[256];
    __shared__ int red[256];
    int t = threadIdx.x, b = blockIdx.x;
    int i = b * 256 + t;
    int v = (i < n) ? g_deg[i] : 0;
    sh[t] = v;
    __syncthreads();
    for (int o = 1; o < 256; o <<= 1) {
        int u = (t >= o) ? sh[t - o] : 0;
        __syncthreads();
        sh[t] += u;
        __syncthreads();
    }
    if (t == 255) atomicExch(&g_bsum[b], sh[255] + SCAN_FLAG);
    int agg = 0;
    for (int p = t; p < b; p += 256) {
        int val;
        do { val = *(volatile int*)&g_bsum[p]; } while (val < SCAN_FLAG);
        agg += val - SCAN_FLAG;
    }
    red[t] = agg;
    __syncthreads();
    for (int o = 128; o; o >>= 1) {
        if (t < o) red[t] += red[t + o];
        __syncthreads();
    }
    int excl = red[0] + sh[t] - v;
    if (i < n) {
        g_rowptr[i] = excl;
        g_cursor[i] = excl;
        if (i == n - 1) g_rowptr[n] = excl + v;
    }
}

__global__ void scatter_edges_kernel(const int* __restrict__ ei, int E, int n) {
    int i = blockIdx.x * blockDim.x + threadIdx.x;
    if (i < E) {
        int s = ei[i];
        int d = ei[E + i];
        g_csrsrc[atomicAdd(&g_cursor[d], 1)] = s;
    } else if (i < E + n) {
        int v = i - E;
        g_csrsrc[atomicAdd(&g_cursor[v], 1)] = v;   // self loop
    }
}

// ============================================================================
// PERSISTENT bf16-split GEMM + attention. 512 threads / 16 warps per CTA.
// warp w: nquad = w>>2 owns cols [nquad*32, +32) (4 n-tiles);
//         rows = (w&3)*32 .. +31 (two m16 groups).
// 3 passes per mma slot: ah*bh + ah*bl + al*bh (lo*lo dropped, ~2^-16).
// ============================================================================
constexpr uint32_t SMEM_WORDS = 4 * IMG_W + 1024;    // Xh|Xl|Bh|Bl + staging
constexpr uint32_t SMEM_BYTES = SMEM_WORDS * 4;      // 143360

__global__ __launch_bounds__(512) void gemm_mma_kernel(
    const float* __restrict__ X,
    const float4* __restrict__ Wbh_g, const float4* __restrict__ Wbl_g,
    const float* __restrict__ atts, const float* __restrict__ attd,
    float* __restrict__ XL, int n)
{
    extern __shared__ uint32_t smu[];
    uint32_t* Xh = smu;
    uint32_t* Xl = smu + IMG_W;
    uint32_t* Bh = smu + 2 * IMG_W;
    uint32_t* Bl = smu + 3 * IMG_W;
    float* sh_s = (float*)(smu + 4 * IMG_W);   // [4][128]
    float* sh_d = sh_s + 512;

    int tid = threadIdx.x, lane = tid & 31, warp = tid >> 5;
    int gid = lane >> 2, tig = lane & 3;
    int nquad = warp >> 2;                  // 0..3: cols [nquad*32, +32)
    int rbase = (warp & 3) * 32;            // rows [rbase, rbase+32)

    // W images: copied once per CTA (persistent)
    {
        float4* dh = (float4*)Bh;
        float4* dl = (float4*)Bl;
#pragma unroll
        for (int i = 0; i < 5; i++) {
            int idx = tid + i * 512;
            if (idx < IMG_F4) { dh[idx] = Wbh_g[idx]; dl[idx] = Wbl_g[idx]; }
        }
    }

    // att vectors in registers (cols: nquad*32 + nt*8 + tig*2 + {0,1})
    float avs[4][2], avd[4][2];
#pragma unroll
    for (int nt = 0; nt < 4; nt++) {
        int col = nquad * 32 + nt * 8 + tig * 2;
        avs[nt][0] = __ldg(atts + col); avs[nt][1] = __ldg(atts + col + 1);
        avd[nt][0] = __ldg(attd + col); avd[nt][1] = __ldg(attd + col + 1);
    }

    int ntiles = (n + 127) >> 7;

    for (int tile = blockIdx.x; tile < ntiles; tile += gridDim.x) {
        int row0 = tile << 7;

        __syncthreads();   // prev tile fully consumed; W copy on first iter
        // X tile: fp32 loads, bf16 hi/lo split, padded stores (uint2 = 2 words)
        {
            const float4* X4 = (const float4*)X;
#pragma unroll
            for (int i = 0; i < 8; i++) {
                int idx = tid + i * 512;        // 128 rows x 32 float4
                int r = idx >> 5, cc = idx & 31;
                float4 v = make_float4(0.f, 0.f, 0.f, 0.f);
                if (row0 + r < n) v = X4[(size_t)(row0 + r) * 32 + cc];
                uint32_t h0, l0, h1, l1;
                cvt_hi_lo(v.x, v.y, h0, l0);
                cvt_hi_lo(v.z, v.w, h1, l1);
                int w = r * RW + cc * 2;
                *(uint2*)(Xh + w) = make_uint2(h0, h1);
                *(uint2*)(Xl + w) = make_uint2(l0, l1);
            }
        }
        __syncthreads();

        float c[2][4][4];
#pragma unroll
        for (int g = 0; g < 2; g++)
#pragma unroll
            for (int nt = 0; nt < 4; nt++)
                c[g][nt][0] = c[g][nt][1] = c[g][nt][2] = c[g][nt][3] = 0.f;

        int aro = (rbase + gid) * RW + tig;                    // A row base
        int bro = (nquad * 32 + gid) * RW + tig;               // B row base

#pragma unroll
        for (int ks = 0; ks < 8; ks++) {
            int kw = ks * 8;
            uint32_t ah[2][4], al[2][4];
#pragma unroll
            for (int g = 0; g < 2; g++) {
                int o = aro + g * (16 * RW) + kw;
                ah[g][0] = Xh[o];              al[g][0] = Xl[o];
                ah[g][1] = Xh[o + 8 * RW];     al[g][1] = Xl[o + 8 * RW];
                ah[g][2] = Xh[o + 4];          al[g][2] = Xl[o + 4];
                ah[g][3] = Xh[o + 8 * RW + 4]; al[g][3] = Xl[o + 8 * RW + 4];
            }
#pragma unroll
            for (int nt = 0; nt < 4; nt++) {
                int o = bro + nt * (8 * RW) + kw;
                uint32_t bh0 = Bh[o], bh1 = Bh[o + 4];
                uint32_t bl0 = Bl[o], bl1 = Bl[o + 4];
                mma_bf16(c[0][nt], ah[0], bh0, bh1);
                mma_bf16(c[0][nt], ah[0], bl0, bl1);
                mma_bf16(c[0][nt], al[0], bh0, bh1);
                mma_bf16(c[1][nt], ah[1], bh0, bh1);
                mma_bf16(c[1][nt], ah[1], bl0, bl1);
                mma_bf16(c[1][nt], al[1], bh0, bh1);
            }
        }

        // Epilogue: per-quad attention dots -> staging; fp32 XL stores.
#pragma unroll
        for (int g = 0; g < 2; g++) {
            float ps0 = 0.f, pd0 = 0.f, ps1 = 0.f, pd1 = 0.f;
#pragma unroll
            for (int nt = 0; nt < 4; nt++) {
                ps0 = fmaf(c[g][nt][0], avs[nt][0], fmaf(c[g][nt][1], avs[nt][1], ps0));
                pd0 = fmaf(c[g][nt][0], avd[nt][0], fmaf(c[g][nt][1], avd[nt][1], pd0));
                ps1 = fmaf(c[g][nt][2], avs[nt][0], fmaf(c[g][nt][3], avs[nt][1], ps1));
                pd1 = fmaf(c[g][nt][2], avd[nt][0], fmaf(c[g][nt][3], avd[nt][1], pd1));
            }
#pragma unroll
            for (int o = 1; o <= 2; o <<= 1) {
                ps0 += __shfl_xor_sync(0xffffffffu, ps0, o);
                pd0 += __shfl_xor_sync(0xffffffffu, pd0, o);
                ps1 += __shfl_xor_sync(0xffffffffu, ps1, o);
                pd1 += __shfl_xor_sync(0xffffffffu, pd1, o);
            }
            int rloc = rbase + g * 16 + gid;
            if (tig == 0) {
                sh_s[nquad * 128 + rloc]     = ps0;
                sh_d[nquad * 128 + rloc]     = pd0;
                sh_s[nquad * 128 + rloc + 8] = ps1;
                sh_d[nquad * 128 + rloc + 8] = pd1;
            }
            int r0 = row0 + rloc;
            int r1 = r0 + 8;
            if (r0 < n) {
                float* dst = XL + (size_t)r0 * 128 + nquad * 32 + tig * 2;
#pragma unroll
                for (int nt = 0; nt < 4; nt++)
                    *(float2*)(dst + nt * 8) = make_float2(c[g][nt][0], c[g][nt][1]);
            }
            if (r1 < n) {
                float* dst = XL + (size_t)r1 * 128 + nquad * 32 + tig * 2;
#pragma unroll
                for (int nt = 0; nt < 4; nt++)
                    *(float2*)(dst + nt * 8) = make_float2(c[g][nt][2], c[g][nt][3]);
            }
        }

        __syncthreads();   // staging complete
        if (tid < 128) {
            int r = row0 + tid;
            if (r < n) {
                g_as[r] = (sh_s[tid] + sh_s[128 + tid]) + (sh_s[256 + tid] + sh_s[384 + tid]);
                g_ad[r] = (sh_d[tid] + sh_d[128 + tid]) + (sh_d[256 + tid] + sh_d[384 + tid]);
            }
        }
    }
}

// ============================================================================
// Aggregation (softmax weight inlined): one warp per dst node.
// ============================================================================
__device__ __forceinline__ float edge_w(float as_v, float adv) {
    float t = as_v + adv;
    t = t > 0.f ? t : 0.2f * t;
    return __expf(t);
}

__global__ __launch_bounds__(256) void aggregate_kernel(
    const float* __restrict__ XL, const float* __restrict__ bias,
    float* __restrict__ OUT, int n)
{
    int wid = blockIdx.x * 8 + (threadIdx.x >> 5);
    int lane = threadIdx.x & 31;
    if (wid >= n) return;

    int beg = g_rowptr[wid];
    int end = g_rowptr[wid + 1];
    float adv = g_ad[wid];
    float4 acc = make_float4(0.f, 0.f, 0.f, 0.f);
    float z = 0.f;
    const float4* XL4 = (const float4*)XL;

    int j = beg;
    for (; j + 4 <= end; j += 4) {
        int s0 = g_csrsrc[j],     s1 = g_csrsrc[j + 1];
        int s2 = g_csrsrc[j + 2], s3 = g_csrsrc[j + 3];
        float w0 = edge_w(g_as[s0], adv);
        float w1 = edge_w(g_as[s1], adv);
        float w2 = edge_w(g_as[s2], adv);
        float w3 = edge_w(g_as[s3], adv);
        float4 x0 = XL4[(size_t)s0 * 32 + lane];
        float4 x1 = XL4[(size_t)s1 * 32 + lane];
        float4 x2 = XL4[(size_t)s2 * 32 + lane];
        float4 x3 = XL4[(size_t)s3 * 32 + lane];
        acc.x = fmaf(w0, x0.x, acc.x); acc.y = fmaf(w0, x0.y, acc.y);
        acc.z = fmaf(w0, x0.z, acc.z); acc.w = fmaf(w0, x0.w, acc.w);
        acc.x = fmaf(w1, x1.x, acc.x); acc.y = fmaf(w1, x1.y, acc.y);
        acc.z = fmaf(w1, x1.z, acc.z); acc.w = fmaf(w1, x1.w, acc.w);
        acc.x = fmaf(w2, x2.x, acc.x); acc.y = fmaf(w2, x2.y, acc.y);
        acc.z = fmaf(w2, x2.z, acc.z); acc.w = fmaf(w2, x2.w, acc.w);
        acc.x = fmaf(w3, x3.x, acc.x); acc.y = fmaf(w3, x3.y, acc.y);
        acc.z = fmaf(w3, x3.z, acc.z); acc.w = fmaf(w3, x3.w, acc.w);
        z += (w0 + w1) + (w2 + w3);
    }
    for (; j < end; j++) {
        int s = g_csrsrc[j];
        float w = edge_w(g_as[s], adv);
        float4 xv = XL4[(size_t)s * 32 + lane];
        acc.x = fmaf(w, xv.x, acc.x); acc.y = fmaf(w, xv.y, acc.y);
        acc.z = fmaf(w, xv.z, acc.z); acc.w = fmaf(w, xv.w, acc.w);
        z += w;
    }

    float inv = 1.f / (z + 1e-16f);
    float4 bv = ((const float4*)bias)[lane];
    float4 o;
    o.x = fmaxf(fmaf(acc.x, inv, bv.x), 0.f);
    o.y = fmaxf(fmaf(acc.y, inv, bv.y), 0.f);
    o.z = fmaxf(fmaf(acc.z, inv, bv.z), 0.f);
    o.w = fmaxf(fmaf(acc.w, inv, bv.w), 0.f);
    ((float4*)OUT)[(size_t)wid * 32 + lane] = o;
}

// ============================================================================
// Launch (8 kernels). gemm1 kept at slot 4 (the profiled slot).
// ============================================================================
extern "C" void kernel_launch(void* const* d_in, const int* in_sizes, int n_in,
                              void* d_out, int out_size)
{
    const float* x   = (const float*)d_in[0];
    const int*   ei  = (const int*)d_in[1];
    const float* W1  = (const float*)d_in[2];
    const float* as1 = (const float*)d_in[3];
    const float* ad1 = (const float*)d_in[4];
    const float* b1  = (const float*)d_in[5];
    const float* W2  = (const float*)d_in[6];
    const float* as2 = (const float*)d_in[7];
    const float* ad2 = (const float*)d_in[8];
    const float* b2  = (const float*)d_in[9];

    int n = in_sizes[0] / DDIM;   // 50000
    int E = in_sizes[1] / 2;      // 800000
    int ee = E + n;
    float* out = (float*)d_out;

    void *xl_p, *h_p, *wh_p, *wl_p;
    cudaGetSymbolAddress(&xl_p, g_xl);
    cudaGetSymbolAddress(&h_p,  g_h);
    cudaGetSymbolAddress(&wh_p, g_wbh);
    cudaGetSymbolAddress(&wl_p, g_wbl);
    float* xl = (float*)xl_p;
    float* h  = (float*)h_p;
    const __nv_bfloat16* wbh = (const __nv_bfloat16*)wh_p;
    const __nv_bfloat16* wbl = (const __nv_bfloat16*)wl_p;

    cudaFuncSetAttribute(gemm_mma_kernel, cudaFuncAttributeMaxDynamicSharedMemorySize, SMEM_BYTES);

    int nb = (n + 255) / 256;     // 196

    // --- prep & CSR build (gemm1 at slot 4 for profiling) ---
    prep_kernel<<<128 + nb, 256>>>(W1, W2, n);
    count_deg_kernel<<<(E + 255) / 256, 256>>>(ei, E);
    scan_rowptr_kernel<<<nb, 256>>>(n);
    gemm_mma_kernel<<<GEMM_GRID, 512, SMEM_BYTES>>>(
        x, (const float4*)wbh, (const float4*)wbl, as1, ad1, xl, n);
    scatter_edges_kernel<<<(ee + 255) / 256, 256>>>(ei, E, n);

    // --- Layer 1 aggregate ---
    aggregate_kernel<<<(n + 7) / 8, 256>>>(xl, b1, h, n);

    // --- Layer 2 ---
    gemm_mma_kernel<<<GEMM_GRID, 512, SMEM_BYTES>>>(
        h, (const float4*)(wbh + 128 * 136), (const float4*)(wbl + 128 * 136),
        as2, ad2, xl, n);
    aggregate_kernel<<<(n + 7) / 8, 256>>>(xl, b2, out, n);
}

// round 14
// speedup vs baseline: 1.2775x; 1.0278x over previous
#include <cuda_runtime.h>
#include <cuda_bf16.h>
#include <cstdint>

// Problem constants: N=50000 nodes, E=800000 edges, D=C=128, H=1
#define NMAX 50000
#define EMAX 800000
#define EE   (EMAX + NMAX)
constexpr int DDIM = 128;
constexpr int SCAN_FLAG = 1 << 30;
constexpr int GEMM_GRID = 148;     // persistent: one CTA per SM

// bf16 tile layout: 136 bf16 per row (pad) = 68 32-bit words; bank = 4*gid+tig
constexpr int RW = 68;             // words per row
constexpr int IMG_W = 128 * RW;    // 8704 words per 128-row bf16 image
constexpr int IMG_F4 = IMG_W / 4;  // 2176 float4 per image

// ---------------- static device scratch ----------------
__device__ float g_xl[(size_t)NMAX * 128];
__device__ float g_h [(size_t)NMAX * 128];
__device__ float g_as[NMAX];
__device__ float g_ad[NMAX];
__device__ int   g_deg[NMAX];
__device__ int   g_rowptr[NMAX + 1];
__device__ int   g_cursor[NMAX];
__device__ int   g_csrsrc[EE];
__device__ int   g_bsum[256];
// W per layer, TRANSPOSED [n][k], bf16 hi/lo, padded rows (136 bf16)
__device__ __align__(16) __nv_bfloat16 g_wbh[2][128 * 136];
__device__ __align__(16) __nv_bfloat16 g_wbl[2][128 * 136];

// ---------------- helpers ----------------
__device__ __forceinline__ void cvt_hi_lo(float a, float b, uint32_t& hi, uint32_t& lo) {
    __nv_bfloat16 ha = __float2bfloat16_rn(a), hb = __float2bfloat16_rn(b);
    float ra = a - __bfloat162float(ha), rb = b - __bfloat162float(hb);
    __nv_bfloat16 la = __float2bfloat16_rn(ra), lb = __float2bfloat16_rn(rb);
    hi = ((uint32_t)(*(unsigned short*)&hb) << 16) | (*(unsigned short*)&ha);
    lo = ((uint32_t)(*(unsigned short*)&lb) << 16) | (*(unsigned short*)&la);
}
__device__ __forceinline__ void mma_bf16(float c[4], const uint32_t a[4], uint32_t b0, uint32_t b1) {
    asm volatile(
        "mma.sync.aligned.m16n8k16.row.col.f32.bf16.bf16.f32 "
        "{%0,%1,%2,%3}, {%4,%5,%6,%7}, {%8,%9}, {%0,%1,%2,%3};"
        : "+f"(c[0]), "+f"(c[1]), "+f"(c[2]), "+f"(c[3])
        : "r"(a[0]), "r"(a[1]), "r"(a[2]), "r"(a[3]), "r"(b0), "r"(b1));
}

// ============================================================================
// Fused prep: blocks [0,128) build W^T bf16 hi/lo images; blocks [128,128+nb)
// init g_deg = 1 (self loop pre-counted); block 128 zeroes scan state.
// ============================================================================
__global__ void prep_kernel(const float* __restrict__ W1, const float* __restrict__ W2, int n) {
    int b = blockIdx.x, t = threadIdx.x;
    if (b < 128) {
        int idx = b * 256 + t;                 // 0..32767
        int layer = idx >> 14;
        int e = idx & 16383;
        int nn = e >> 7, k = e & 127;          // write coalesced in k
        float v = (layer ? W2 : W1)[k * 128 + nn];
        __nv_bfloat16 h = __float2bfloat16_rn(v);
        float r = v - __bfloat162float(h);
        g_wbh[layer][nn * 136 + k] = h;
        g_wbl[layer][nn * 136 + k] = __float2bfloat16_rn(r);
    } else {
        int i = (b - 128) * 256 + t;
        if (i < n) g_deg[i] = 1;               // self loop
        if (b == 128) g_bsum[t] = 0;
    }
}

// ============================================================================
// CSR build
// ============================================================================
__global__ void count_deg_kernel(const int* __restrict__ ei, int E) {
    int i = blockIdx.x * blockDim.x + threadIdx.x;
    if (i < E) atomicAdd(&g_deg[ei[E + i]], 1);
}

__global__ void scan_rowptr_kernel(int n) {
    __shared__ int sh[256];
    __shared__ int red[256];
    int t = threadIdx.x, b = blockIdx.x;
    int i = b * 256 + t;
    int v = (i < n) ? g_deg[i] : 0;
    sh[t] = v;
    __syncthreads();
    for (int o = 1; o < 256; o <<= 1) {
        int u = (t >= o) ? sh[t - o] : 0;
        __syncthreads();
        sh[t] += u;
        __syncthreads();
    }
    if (t == 255) atomicExch(&g_bsum[b], sh[255] + SCAN_FLAG);
    int agg = 0;
    for (int p = t; p < b; p += 256) {
        int val;
        do { val = *(volatile int*)&g_bsum[p]; } while (val < SCAN_FLAG);
        agg += val - SCAN_FLAG;
    }
    red[t] = agg;
    __syncthreads();
    for (int o = 128; o; o >>= 1) {
        if (t < o) red[t] += red[t + o];
        __syncthreads();
    }
    int excl = red[0] + sh[t] - v;
    if (i < n) {
        g_rowptr[i] = excl;
        g_cursor[i] = excl;
        if (i == n - 1) g_rowptr[n] = excl + v;
    }
}

__global__ void scatter_edges_kernel(const int* __restrict__ ei, int E, int n) {
    int i = blockIdx.x * blockDim.x + threadIdx.x;
    if (i < E) {
        int s = ei[i];
        int d = ei[E + i];
        g_csrsrc[atomicAdd(&g_cursor[d], 1)] = s;
    } else if (i < E + n) {
        int v = i - E;
        g_csrsrc[atomicAdd(&g_cursor[v], 1)] = v;   // self loop
    }
}

// ============================================================================
// PERSISTENT bf16-split GEMM + attention, SOFTWARE-PIPELINED.
// 512 threads / 16 warps. Double-buffered X (hi/lo); next tile prefetched
// into registers (2 chunks of 4 float4) during current tile's MMA compute,
// converted + stored to the inactive buffer. ONE sync per tile.
// ============================================================================
constexpr uint32_t SMEM_WORDS = 6 * IMG_W + 1024;    // X0h|X0l|X1h|X1l|Bh|Bl + staging
constexpr uint32_t SMEM_BYTES = SMEM_WORDS * 4;      // 212992

__global__ __launch_bounds__(512) void gemm_mma_kernel(
    const float* __restrict__ X,
    const float4* __restrict__ Wbh_g, const float4* __restrict__ Wbl_g,
    const float* __restrict__ atts, const float* __restrict__ attd,
    float* __restrict__ XL, int n)
{
    extern __shared__ uint32_t smu[];
    uint32_t* Xb[2][2];
    Xb[0][0] = smu;                 // X0 hi
    Xb[0][1] = smu + IMG_W;         // X0 lo
    Xb[1][0] = smu + 2 * IMG_W;     // X1 hi
    Xb[1][1] = smu + 3 * IMG_W;     // X1 lo
    uint32_t* Bh = smu + 4 * IMG_W;
    uint32_t* Bl = smu + 5 * IMG_W;
    float* sh_s = (float*)(smu + 6 * IMG_W);   // [4][128]
    float* sh_d = sh_s + 512;

    int tid = threadIdx.x, lane = tid & 31, warp = tid >> 5;
    int gid = lane >> 2, tig = lane & 3;
    int nquad = warp >> 2;                  // 0..3: cols [nquad*32, +32)
    int rbase = (warp & 3) * 32;            // rows [rbase, rbase+32)

    // W images: copied once per CTA (persistent)
    {
        float4* dh = (float4*)Bh;
        float4* dl = (float4*)Bl;
#pragma unroll
        for (int i = 0; i < 5; i++) {
            int idx = tid + i * 512;
            if (idx < IMG_F4) { dh[idx] = Wbh_g[idx]; dl[idx] = Wbl_g[idx]; }
        }
    }

    // att vectors in registers
    float avs[4][2], avd[4][2];
#pragma unroll
    for (int nt = 0; nt < 4; nt++) {
        int col = nquad * 32 + nt * 8 + tig * 2;
        avs[nt][0] = __ldg(atts + col); avs[nt][1] = __ldg(atts + col + 1);
        avd[nt][0] = __ldg(attd + col); avd[nt][1] = __ldg(attd + col + 1);
    }

    const float4* X4 = (const float4*)X;
    int ntiles = (n + 127) >> 7;
    // thread's fixed (row, col) slots for X loading: 8 float4, 2 chunks of 4
    int lr[8], lc[8];
#pragma unroll
    for (int j = 0; j < 8; j++) {
        int idx = tid + j * 512;
        lr[j] = idx >> 5; lc[j] = idx & 31;
    }

    // Prologue: load first tile into buffer 0
    {
        int row0 = blockIdx.x << 7;
#pragma unroll
        for (int j = 0; j < 8; j++) {
            float4 v = make_float4(0.f, 0.f, 0.f, 0.f);
            if (row0 + lr[j] < n) v = X4[(size_t)(row0 + lr[j]) * 32 + lc[j]];
            uint32_t h0, l0, h1, l1;
            cvt_hi_lo(v.x, v.y, h0, l0);
            cvt_hi_lo(v.z, v.w, h1, l1);
            int w = lr[j] * RW + lc[j] * 2;
            *(uint2*)(Xb[0][0] + w) = make_uint2(h0, h1);
            *(uint2*)(Xb[0][1] + w) = make_uint2(l0, l1);
        }
    }
    __syncthreads();

    int buf = 0;
    for (int tile = blockIdx.x; tile < ntiles; tile += gridDim.x, buf ^= 1) {
        int row0 = tile << 7;
        uint32_t* Xh = Xb[buf][0];
        uint32_t* Xl = Xb[buf][1];
        uint32_t* Yh = Xb[buf ^ 1][0];
        uint32_t* Yl = Xb[buf ^ 1][1];
        int nrow0 = (tile + gridDim.x) << 7;
        bool have_next = (tile + gridDim.x) < ntiles;

        float c[2][4][4];
#pragma unroll
        for (int g = 0; g < 2; g++)
#pragma unroll
            for (int nt = 0; nt < 4; nt++)
                c[g][nt][0] = c[g][nt][1] = c[g][nt][2] = c[g][nt][3] = 0.f;

        int aro = (rbase + gid) * RW + tig;
        int bro = (nquad * 32 + gid) * RW + tig;

        // ---- chunk 0 prefetch (next tile, float4 slots 0..3) ----
        float4 pv[4];
        if (have_next) {
#pragma unroll
            for (int j = 0; j < 4; j++) {
                pv[j] = make_float4(0.f, 0.f, 0.f, 0.f);
                if (nrow0 + lr[j] < n) pv[j] = X4[(size_t)(nrow0 + lr[j]) * 32 + lc[j]];
            }
        }
        // ---- compute ks 0..3 ----
#pragma unroll
        for (int ks = 0; ks < 4; ks++) {
            int kw = ks * 8;
            uint32_t ah[2][4], al[2][4];
#pragma unroll
            for (int g = 0; g < 2; g++) {
                int o = aro + g * (16 * RW) + kw;
                ah[g][0] = Xh[o];              al[g][0] = Xl[o];
                ah[g][1] = Xh[o + 8 * RW];     al[g][1] = Xl[o + 8 * RW];
                ah[g][2] = Xh[o + 4];          al[g][2] = Xl[o + 4];
                ah[g][3] = Xh[o + 8 * RW + 4]; al[g][3] = Xl[o + 8 * RW + 4];
            }
#pragma unroll
            for (int nt = 0; nt < 4; nt++) {
                int o = bro + nt * (8 * RW) + kw;
                uint32_t bh0 = Bh[o], bh1 = Bh[o + 4];
                uint32_t bl0 = Bl[o], bl1 = Bl[o + 4];
                mma_bf16(c[0][nt], ah[0], bh0, bh1);
                mma_bf16(c[0][nt], ah[0], bl0, bl1);
                mma_bf16(c[0][nt], al[0], bh0, bh1);
                mma_bf16(c[1][nt], ah[1], bh0, bh1);
                mma_bf16(c[1][nt], ah[1], bl0, bl1);
                mma_bf16(c[1][nt], al[1], bh0, bh1);
            }
        }
        // ---- chunk 0 convert + store into inactive buffer ----
        if (have_next) {
#pragma unroll
            for (int j = 0; j < 4; j++) {
                uint32_t h0, l0, h1, l1;
                cvt_hi_lo(pv[j].x, pv[j].y, h0, l0);
                cvt_hi_lo(pv[j].z, pv[j].w, h1, l1);
                int w = lr[j] * RW + lc[j] * 2;
                *(uint2*)(Yh + w) = make_uint2(h0, h1);
                *(uint2*)(Yl + w) = make_uint2(l0, l1);
            }
            // ---- chunk 1 prefetch ----
#pragma unroll
            for (int j = 0; j < 4; j++) {
                pv[j] = make_float4(0.f, 0.f, 0.f, 0.f);
                if (nrow0 + lr[j + 4] < n) pv[j] = X4[(size_t)(nrow0 + lr[j + 4]) * 32 + lc[j + 4]];
            }
        }
        // ---- compute ks 4..7 ----
#pragma unroll
        for (int ks = 4; ks < 8; ks++) {
            int kw = ks * 8;
            uint32_t ah[2][4], al[2][4];
#pragma unroll
            for (int g = 0; g < 2; g++) {
                int o = aro + g * (16 * RW) + kw;
                ah[g][0] = Xh[o];              al[g][0] = Xl[o];
                ah[g][1] = Xh[o + 8 * RW];     al[g][1] = Xl[o + 8 * RW];
                ah[g][2] = Xh[o + 4];          al[g][2] = Xl[o + 4];
                ah[g][3] = Xh[o + 8 * RW + 4]; al[g][3] = Xl[o + 8 * RW + 4];
            }
#pragma unroll
            for (int nt = 0; nt < 4; nt++) {
                int o = bro + nt * (8 * RW) + kw;
                uint32_t bh0 = Bh[o], bh1 = Bh[o + 4];
                uint32_t bl0 = Bl[o], bl1 = Bl[o + 4];
                mma_bf16(c[0][nt], ah[0], bh0, bh1);
                mma_bf16(c[0][nt], ah[0], bl0, bl1);
                mma_bf16(c[0][nt], al[0], bh0, bh1);
                mma_bf16(c[1][nt], ah[1], bh0, bh1);
                mma_bf16(c[1][nt], ah[1], bl0, bl1);
                mma_bf16(c[1][nt], al[1], bh0, bh1);
            }
        }
        // ---- chunk 1 convert + store ----
        if (have_next) {
#pragma unroll
            for (int j = 0; j < 4; j++) {
                uint32_t h0, l0, h1, l1;
                cvt_hi_lo(pv[j].x, pv[j].y, h0, l0);
                cvt_hi_lo(pv[j].z, pv[j].w, h1, l1);
                int w = lr[j + 4] * RW + lc[j + 4] * 2;
                *(uint2*)(Yh + w) = make_uint2(h0, h1);
                *(uint2*)(Yl + w) = make_uint2(l0, l1);
            }
        }

        // ---- epilogue: attention dots -> staging; fp32 XL stores ----
#pragma unroll
        for (int g = 0; g < 2; g++) {
            float ps0 = 0.f, pd0 = 0.f, ps1 = 0.f, pd1 = 0.f;
#pragma unroll
            for (int nt = 0; nt < 4; nt++) {
                ps0 = fmaf(c[g][nt][0], avs[nt][0], fmaf(c[g][nt][1], avs[nt][1], ps0));
                pd0 = fmaf(c[g][nt][0], avd[nt][0], fmaf(c[g][nt][1], avd[nt][1], pd0));
                ps1 = fmaf(c[g][nt][2], avs[nt][0], fmaf(c[g][nt][3], avs[nt][1], ps1));
                pd1 = fmaf(c[g][nt][2], avd[nt][0], fmaf(c[g][nt][3], avd[nt][1], pd1));
            }
#pragma unroll
            for (int o = 1; o <= 2; o <<= 1) {
                ps0 += __shfl_xor_sync(0xffffffffu, ps0, o);
                pd0 += __shfl_xor_sync(0xffffffffu, pd0, o);
                ps1 += __shfl_xor_sync(0xffffffffu, ps1, o);
                pd1 += __shfl_xor_sync(0xffffffffu, pd1, o);
            }
            int rloc = rbase + g * 16 + gid;
            if (tig == 0) {
                sh_s[nquad * 128 + rloc]     = ps0;
                sh_d[nquad * 128 + rloc]     = pd0;
                sh_s[nquad * 128 + rloc + 8] = ps1;
                sh_d[nquad * 128 + rloc + 8] = pd1;
            }
            int r0 = row0 + rloc;
            int r1 = r0 + 8;
            if (r0 < n) {
                float* dst = XL + (size_t)r0 * 128 + nquad * 32 + tig * 2;
#pragma unroll
                for (int nt = 0; nt < 4; nt++)
                    *(float2*)(dst + nt * 8) = make_float2(c[g][nt][0], c[g][nt][1]);
            }
            if (r1 < n) {
                float* dst = XL + (size_t)r1 * 128 + nquad * 32 + tig * 2;
#pragma unroll
                for (int nt = 0; nt < 4; nt++)
                    *(float2*)(dst + nt * 8) = make_float2(c[g][nt][2], c[g][nt][3]);
            }
        }

        // ONE sync: staging complete + next buffer written + cur buffer free
        __syncthreads();
        if (tid < 128) {
            int r = row0 + tid;
            if (r < n) {
                g_as[r] = (sh_s[tid] + sh_s[128 + tid]) + (sh_s[256 + tid] + sh_s[384 + tid]);
                g_ad[r] = (sh_d[tid] + sh_d[128 + tid]) + (sh_d[256 + tid] + sh_d[384 + tid]);
            }
        }
    }
}

// ============================================================================
// Aggregation (softmax weight inlined): one warp per dst node.
// ============================================================================
__device__ __forceinline__ float edge_w(float as_v, float adv) {
    float t = as_v + adv;
    t = t > 0.f ? t : 0.2f * t;
    return __expf(t);
}

__global__ __launch_bounds__(256) void aggregate_kernel(
    const float* __restrict__ XL, const float* __restrict__ bias,
    float* __restrict__ OUT, int n)
{
    int wid = blockIdx.x * 8 + (threadIdx.x >> 5);
    int lane = threadIdx.x & 31;
    if (wid >= n) return;

    int beg = g_rowptr[wid];
    int end = g_rowptr[wid + 1];
    float adv = g_ad[wid];
    float4 acc = make_float4(0.f, 0.f, 0.f, 0.f);
    float z = 0.f;
    const float4* XL4 = (const float4*)XL;

    int j = beg;
    for (; j + 4 <= end; j += 4) {
        int s0 = g_csrsrc[j],     s1 = g_csrsrc[j + 1];
        int s2 = g_csrsrc[j + 2], s3 = g_csrsrc[j + 3];
        float w0 = edge_w(g_as[s0], adv);
        float w1 = edge_w(g_as[s1], adv);
        float w2 = edge_w(g_as[s2], adv);
        float w3 = edge_w(g_as[s3], adv);
        float4 x0 = XL4[(size_t)s0 * 32 + lane];
        float4 x1 = XL4[(size_t)s1 * 32 + lane];
        float4 x2 = XL4[(size_t)s2 * 32 + lane];
        float4 x3 = XL4[(size_t)s3 * 32 + lane];
        acc.x = fmaf(w0, x0.x, acc.x); acc.y = fmaf(w0, x0.y, acc.y);
        acc.z = fmaf(w0, x0.z, acc.z); acc.w = fmaf(w0, x0.w, acc.w);
        acc.x = fmaf(w1, x1.x, acc.x); acc.y = fmaf(w1, x1.y, acc.y);
        acc.z = fmaf(w1, x1.z, acc.z); acc.w = fmaf(w1, x1.w, acc.w);
        acc.x = fmaf(w2, x2.x, acc.x); acc.y = fmaf(w2, x2.y, acc.y);
        acc.z = fmaf(w2, x2.z, acc.z); acc.w = fmaf(w2, x2.w, acc.w);
        acc.x = fmaf(w3, x3.x, acc.x); acc.y = fmaf(w3, x3.y, acc.y);
        acc.z = fmaf(w3, x3.z, acc.z); acc.w = fmaf(w3, x3.w, acc.w);
        z += (w0 + w1) + (w2 + w3);
    }
    for (; j < end; j++) {
        int s = g_csrsrc[j];
        float w = edge_w(g_as[s], adv);
        float4 xv = XL4[(size_t)s * 32 + lane];
        acc.x = fmaf(w, xv.x, acc.x); acc.y = fmaf(w, xv.y, acc.y);
        acc.z = fmaf(w, xv.z, acc.z); acc.w = fmaf(w, xv.w, acc.w);
        z += w;
    }

    float inv = 1.f / (z + 1e-16f);
    float4 bv = ((const float4*)bias)[lane];
    float4 o;
    o.x = fmaxf(fmaf(acc.x, inv, bv.x), 0.f);
    o.y = fmaxf(fmaf(acc.y, inv, bv.y), 0.f);
    o.z = fmaxf(fmaf(acc.z, inv, bv.z), 0.f);
    o.w = fmaxf(fmaf(acc.w, inv, bv.w), 0.f);
    ((float4*)OUT)[(size_t)wid * 32 + lane] = o;
}

// ============================================================================
// Launch (8 kernels). gemm1 kept at slot 4 (the profiled slot).
// ============================================================================
extern "C" void kernel_launch(void* const* d_in, const int* in_sizes, int n_in,
                              void* d_out, int out_size)
{
    const float* x   = (const float*)d_in[0];
    const int*   ei  = (const int*)d_in[1];
    const float* W1  = (const float*)d_in[2];
    const float* as1 = (const float*)d_in[3];
    const float* ad1 = (const float*)d_in[4];
    const float* b1  = (const float*)d_in[5];
    const float* W2  = (const float*)d_in[6];
    const float* as2 = (const float*)d_in[7];
    const float* ad2 = (const float*)d_in[8];
    const float* b2  = (const float*)d_in[9];

    int n = in_sizes[0] / DDIM;   // 50000
    int E = in_sizes[1] / 2;      // 800000
    int ee = E + n;
    float* out = (float*)d_out;

    void *xl_p, *h_p, *wh_p, *wl_p;
    cudaGetSymbolAddress(&xl_p, g_xl);
    cudaGetSymbolAddress(&h_p,  g_h);
    cudaGetSymbolAddress(&wh_p, g_wbh);
    cudaGetSymbolAddress(&wl_p, g_wbl);
    float* xl = (float*)xl_p;
    float* h  = (float*)h_p;
    const __nv_bfloat16* wbh = (const __nv_bfloat16*)wh_p;
    const __nv_bfloat16* wbl = (const __nv_bfloat16*)wl_p;

    cudaFuncSetAttribute(gemm_mma_kernel, cudaFuncAttributeMaxDynamicSharedMemorySize, SMEM_BYTES);

    int nb = (n + 255) / 256;     // 196

    // --- prep & CSR build (gemm1 at slot 4 for profiling) ---
    prep_kernel<<<128 + nb, 256>>>(W1, W2, n);
    count_deg_kernel<<<(E + 255) / 256, 256>>>(ei, E);
    scan_rowptr_kernel<<<nb, 256>>>(n);
    gemm_mma_kernel<<<GEMM_GRID, 512, SMEM_BYTES>>>(
        x, (const float4*)wbh, (const float4*)wbl, as1, ad1, xl, n);
    scatter_edges_kernel<<<(ee + 255) / 256, 256>>>(ei, E, n);

    // --- Layer 1 aggregate ---
    aggregate_kernel<<<(n + 7) / 8, 256>>>(xl, b1, h, n);

    // --- Layer 2 ---
    gemm_mma_kernel<<<GEMM_GRID, 512, SMEM_BYTES>>>(
        h, (const float4*)(wbh + 128 * 136), (const float4*)(wbl + 128 * 136),
        as2, ad2, xl, n);
    aggregate_kernel<<<(n + 7) / 8, 256>>>(xl, b2, out, n);
}